// round 1
// baseline (speedup 1.0000x reference)
#include <cuda_runtime.h>

#define D 128
#define MAXN 50000

// Scratch (device globals: no allocation allowed)
__device__ float g_dinv[MAXN];
__device__ float g_gbuf[(size_t)MAXN * D];
__device__ float g_agg1[(size_t)MAXN * D];
__device__ float g_h1[(size_t)MAXN * D];
__device__ int   g_is32;

// ---------------------------------------------------------------------------
// edge_index dtype detection: reference says int64, but if the harness ran JAX
// without x64, it is int32. Reading int32 data as int64 packs two indices into
// one word -> values >= 2^32 >= n with overwhelming probability.
__global__ void detect_kernel(const long long* __restrict__ ei, int E, int n) {
    if (blockIdx.x == 0 && threadIdx.x == 0) {
        int is32 = 0;
        int m = E < 64 ? E : 64;
        for (int i = 0; i < m; i++) {
            long long v = ei[i];
            if (v < 0 || v >= (long long)n) { is32 = 1; break; }
        }
        g_is32 = is32;
    }
}

__device__ __forceinline__ int load_idx(const void* ei, size_t pos) {
    if (g_is32) return ((const int*)ei)[pos];
    return (int)((const long long*)ei)[pos];
}

// ---------------------------------------------------------------------------
__global__ void deg_init_kernel(float* deg, int n) {
    int i = blockIdx.x * blockDim.x + threadIdx.x;
    if (i < n) deg[i] = 1.0f;   // self-loop
}

__global__ void deg_count_kernel(const void* __restrict__ ei, float* deg, int E) {
    int e = blockIdx.x * blockDim.x + threadIdx.x;
    if (e < E) {
        int d = load_idx(ei, (size_t)E + e);
        atomicAdd(&deg[d], 1.0f);
    }
}

__global__ void dinv_kernel(float* d, int n) {
    int i = blockIdx.x * blockDim.x + threadIdx.x;
    if (i < n) d[i] = rsqrtf(d[i]);
}

// ---------------------------------------------------------------------------
// g = (X @ W) * dinv[row]; also agg = g (self-loop contribution as init).
// Block: 256 threads. 32 rows per block, thread = (col j in 0..127, row-group rg in 0..1).
// K split into two 64-chunks so static smem stays under 48KB.
__global__ void gemm_scale_kernel(const float* __restrict__ X,
                                  const float* __restrict__ W,
                                  const float* __restrict__ dinv,
                                  float* __restrict__ g,
                                  float* __restrict__ agg, int n) {
    __shared__ float Ws[64][D];     // 32 KB
    __shared__ float Xs[32][64];    // 8 KB
    int tid = threadIdx.x;
    int j   = tid & 127;
    int rg  = tid >> 7;             // 0 or 1
    int row0 = blockIdx.x * 32;

    float acc[16];
#pragma unroll
    for (int r = 0; r < 16; r++) acc[r] = 0.f;

    for (int kb = 0; kb < D; kb += 64) {
        // load W tile [64,128]
        for (int i = tid; i < 64 * 128; i += 256)
            Ws[i >> 7][i & 127] = W[(size_t)(kb + (i >> 7)) * D + (i & 127)];
        // load X tile [32,64]
        for (int i = tid; i < 32 * 64; i += 256) {
            int r = i >> 6, k = i & 63;
            int row = row0 + r;
            Xs[r][k] = (row < n) ? X[(size_t)row * D + kb + k] : 0.f;
        }
        __syncthreads();
#pragma unroll 4
        for (int k = 0; k < 64; k++) {
            float w = Ws[k][j];
#pragma unroll
            for (int r = 0; r < 16; r++)
                acc[r] += Xs[rg * 16 + r][k] * w;
        }
        __syncthreads();
    }

#pragma unroll
    for (int r = 0; r < 16; r++) {
        int row = row0 + rg * 16 + r;
        if (row < n) {
            float v = acc[r] * dinv[row];
            g[(size_t)row * D + j]   = v;
            agg[(size_t)row * D + j] = v;
        }
    }
}

// ---------------------------------------------------------------------------
// One warp per edge: agg[dst] += g[src], as 32 x float4 vector atomics.
__global__ void scatter_kernel(const void* __restrict__ ei,
                               const float4* __restrict__ g,
                               float4* __restrict__ agg, int E) {
    long long gt = (long long)blockIdx.x * blockDim.x + threadIdx.x;
    int e    = (int)(gt >> 5);
    int lane = (int)(gt & 31);
    if (e >= E) return;
    int s = load_idx(ei, (size_t)e);
    int d = load_idx(ei, (size_t)E + e);
    float4 v = g[(size_t)s * 32 + lane];
    atomicAdd(&agg[(size_t)d * 32 + lane], v);
}

// ---------------------------------------------------------------------------
__global__ void finalize_kernel(const float* __restrict__ agg,
                                const float* __restrict__ dinv,
                                const float* __restrict__ b,
                                float* __restrict__ out, int n, int do_relu) {
    int i = blockIdx.x * blockDim.x + threadIdx.x;
    if (i >= n * D) return;
    int row = i >> 7, col = i & 127;
    float v = agg[i] * dinv[row] + b[col];
    out[i] = do_relu ? fmaxf(v, 0.f) : v;
}

// ---------------------------------------------------------------------------
extern "C" void kernel_launch(void* const* d_in, const int* in_sizes, int n_in,
                              void* d_out, int out_size) {
    const float* x  = (const float*)d_in[0];
    const void*  ei = (const void*) d_in[1];
    const float* W1 = (const float*)d_in[2];
    const float* b1 = (const float*)d_in[3];
    const float* W2 = (const float*)d_in[4];
    const float* b2 = (const float*)d_in[5];
    float* out = (float*)d_out;

    int n = in_sizes[0] / D;
    int E = in_sizes[1] / 2;

    float *dinv, *gbuf, *agg1, *h1;
    cudaGetSymbolAddress((void**)&dinv, g_dinv);
    cudaGetSymbolAddress((void**)&gbuf, g_gbuf);
    cudaGetSymbolAddress((void**)&agg1, g_agg1);
    cudaGetSymbolAddress((void**)&h1,   g_h1);

    detect_kernel<<<1, 32>>>((const long long*)ei, E, n);

    deg_init_kernel<<<(n + 255) / 256, 256>>>(dinv, n);
    deg_count_kernel<<<(E + 255) / 256, 256>>>(ei, dinv, E);
    dinv_kernel<<<(n + 255) / 256, 256>>>(dinv, n);

    int gblocks = (n + 31) / 32;
    long long st = (long long)E * 32;
    int sblocks = (int)((st + 255) / 256);
    int fblocks = (n * D + 255) / 256;

    // Layer 1
    gemm_scale_kernel<<<gblocks, 256>>>(x, W1, dinv, gbuf, agg1, n);
    scatter_kernel<<<sblocks, 256>>>(ei, (const float4*)gbuf, (float4*)agg1, E);
    finalize_kernel<<<fblocks, 256>>>(agg1, dinv, b1, h1, n, 1);

    // Layer 2 (agg lives directly in d_out; gemm epilogue initializes every element)
    gemm_scale_kernel<<<gblocks, 256>>>(h1, W2, dinv, gbuf, out, n);
    scatter_kernel<<<sblocks, 256>>>(ei, (const float4*)gbuf, (float4*)out, E);
    finalize_kernel<<<fblocks, 256>>>(out, dinv, b2, out, n, 0);
}

// round 2
// speedup vs baseline: 2.0783x; 2.0783x over previous
#include <cuda_runtime.h>

#define D 128
#define MAXN 50048
#define MAXE 800000
#define SCAN_BLK 256
#define NB_SCAN ((MAXN + SCAN_BLK - 1) / SCAN_BLK)

// Scratch (device globals: no allocation allowed)
__device__ float g_dinv[MAXN];
__device__ float g_gbuf[(size_t)MAXN * D];
__device__ float g_h1[(size_t)MAXN * D];
__device__ int   g_cnt[MAXN];
__device__ int   g_off[MAXN];
__device__ int   g_bsum[NB_SCAN];
__device__ int   g_csr[MAXE];
__device__ int   g_is32;

// ---------------------------------------------------------------------------
// edge_index dtype detection: reference says int64, but if JAX ran without
// x64 it is int32. int32 data read as int64 gives values outside [0, n).
__global__ void detect_kernel(const long long* __restrict__ ei, int E, int n) {
    if (threadIdx.x == 0) {
        int is32 = 0;
        int m = E < 64 ? E : 64;
        for (int i = 0; i < m; i++) {
            long long v = ei[i];
            if (v < 0 || v >= (long long)n) { is32 = 1; break; }
        }
        g_is32 = is32;
    }
}

__device__ __forceinline__ int load_idx(const void* ei, size_t pos) {
    if (g_is32) return ((const int*)ei)[pos];
    return (int)((const long long*)ei)[pos];
}

// ---------------------------------------------------------------------------
__global__ void zero_cnt_kernel(int* cnt, int n) {
    int i = blockIdx.x * blockDim.x + threadIdx.x;
    if (i < n) cnt[i] = 0;
}

__global__ void hist_kernel(const void* __restrict__ ei, int* cnt, int E) {
    int e = blockIdx.x * blockDim.x + threadIdx.x;
    if (e < E) atomicAdd(&cnt[load_idx(ei, (size_t)E + e)], 1);
}

__global__ void dinv_kernel(const int* __restrict__ cnt, float* dinv, int n) {
    int i = blockIdx.x * blockDim.x + threadIdx.x;
    if (i < n) dinv[i] = rsqrtf((float)cnt[i] + 1.0f);  // +1 self-loop
}

// ---- exclusive prefix scan over cnt -> off (3 phases) ----------------------
__global__ void scan1_kernel(const int* __restrict__ cnt, int* off, int* bsum, int n) {
    __shared__ int s[SCAN_BLK];
    int i = blockIdx.x * SCAN_BLK + threadIdx.x;
    int v = (i < n) ? cnt[i] : 0;
    s[threadIdx.x] = v;
    __syncthreads();
#pragma unroll
    for (int d = 1; d < SCAN_BLK; d <<= 1) {
        int t = (threadIdx.x >= d) ? s[threadIdx.x - d] : 0;
        __syncthreads();
        s[threadIdx.x] += t;
        __syncthreads();
    }
    if (i < n) off[i] = s[threadIdx.x] - v;       // exclusive
    if (threadIdx.x == SCAN_BLK - 1) bsum[blockIdx.x] = s[SCAN_BLK - 1];
}

__global__ void scan2_kernel(int* bsum, int nb) {
    __shared__ int s[SCAN_BLK];
    int v = (threadIdx.x < nb) ? bsum[threadIdx.x] : 0;
    s[threadIdx.x] = v;
    __syncthreads();
#pragma unroll
    for (int d = 1; d < SCAN_BLK; d <<= 1) {
        int t = (threadIdx.x >= d) ? s[threadIdx.x - d] : 0;
        __syncthreads();
        s[threadIdx.x] += t;
        __syncthreads();
    }
    if (threadIdx.x < nb) bsum[threadIdx.x] = s[threadIdx.x] - v;  // exclusive
}

__global__ void scan3_kernel(int* off, const int* __restrict__ bsum, int n) {
    int i = blockIdx.x * SCAN_BLK + threadIdx.x;
    if (i < n) off[i] += bsum[blockIdx.x];
}

// fill CSR: off is consumed as cursor; afterwards off[j] == end offset of node j
__global__ void fill_kernel(const void* __restrict__ ei, int* off, int* csr, int E) {
    int e = blockIdx.x * blockDim.x + threadIdx.x;
    if (e < E) {
        int s = load_idx(ei, (size_t)e);
        int d = load_idx(ei, (size_t)E + e);
        int pos = atomicAdd(&off[d], 1);
        csr[pos] = s;
    }
}

// ---------------------------------------------------------------------------
// g = (X @ W) * dinv[row].  128x128 block tile, 8x8 per thread, K-chunks of 16.
#define KC 16
__global__ __launch_bounds__(256) void gemm_kernel(const float* __restrict__ X,
                                                   const float* __restrict__ W,
                                                   const float* __restrict__ dinv,
                                                   float* __restrict__ g, int n) {
    __shared__ float Xs[KC][128];   // k-major
    __shared__ float Ws[KC][128];
    int tid = threadIdx.x;
    int tx = tid & 15;
    int ty = tid >> 4;
    int row0 = blockIdx.x * 128;

    float acc[8][8];
#pragma unroll
    for (int i = 0; i < 8; i++)
#pragma unroll
        for (int j = 0; j < 8; j++) acc[i][j] = 0.f;

    for (int kb = 0; kb < D; kb += KC) {
        // load W chunk [KC][128]: 512 float4 by 256 threads
#pragma unroll
        for (int i = tid; i < KC * 32; i += 256) {
            int k = i >> 5, c4 = i & 31;
            ((float4*)Ws[k])[c4] = ((const float4*)(W + (size_t)(kb + k) * D))[c4];
        }
        // load X chunk transposed: 128 rows x KC, float4 along k
#pragma unroll
        for (int i = tid; i < 128 * (KC / 4); i += 256) {
            int r = i >> 2, c = i & 3;
            int row = row0 + r;
            float4 v = (row < n) ? ((const float4*)(X + (size_t)row * D + kb))[c]
                                 : make_float4(0.f, 0.f, 0.f, 0.f);
            Xs[c * 4 + 0][r] = v.x;
            Xs[c * 4 + 1][r] = v.y;
            Xs[c * 4 + 2][r] = v.z;
            Xs[c * 4 + 3][r] = v.w;
        }
        __syncthreads();
#pragma unroll
        for (int k = 0; k < KC; k++) {
            float4 a0 = *(const float4*)&Xs[k][ty * 4];
            float4 a1 = *(const float4*)&Xs[k][64 + ty * 4];
            float4 b0 = *(const float4*)&Ws[k][tx * 4];
            float4 b1 = *(const float4*)&Ws[k][64 + tx * 4];
            float a[8] = {a0.x, a0.y, a0.z, a0.w, a1.x, a1.y, a1.z, a1.w};
            float b[8] = {b0.x, b0.y, b0.z, b0.w, b1.x, b1.y, b1.z, b1.w};
#pragma unroll
            for (int i = 0; i < 8; i++)
#pragma unroll
                for (int j = 0; j < 8; j++) acc[i][j] += a[i] * b[j];
        }
        __syncthreads();
    }

    // epilogue: scale by dinv[row], store
#pragma unroll
    for (int i = 0; i < 8; i++) {
        int row = row0 + ((i < 4) ? (ty * 4 + i) : (64 + ty * 4 + i - 4));
        if (row < n) {
            float dv = dinv[row];
            float4 o0 = make_float4(acc[i][0] * dv, acc[i][1] * dv,
                                    acc[i][2] * dv, acc[i][3] * dv);
            float4 o1 = make_float4(acc[i][4] * dv, acc[i][5] * dv,
                                    acc[i][6] * dv, acc[i][7] * dv);
            *(float4*)(g + (size_t)row * D + tx * 4)      = o0;
            *(float4*)(g + (size_t)row * D + 64 + tx * 4) = o1;
        }
    }
}

// ---------------------------------------------------------------------------
// Pull aggregation: warp per node. out[j] = dinv[j]*(sum_{i->j} g[i] + g[j]) + b
// endoff[j] = end offset (post-fill cursor); start = endoff[j-1].
__global__ void gather_kernel(const int* __restrict__ csr,
                              const int* __restrict__ endoff,
                              const float4* __restrict__ g,
                              const float* __restrict__ dinv,
                              const float* __restrict__ bias,
                              float4* __restrict__ out, int n, int do_relu) {
    int gt = blockIdx.x * blockDim.x + threadIdx.x;
    int node = gt >> 5;
    int lane = gt & 31;
    if (node >= n) return;

    int end = endoff[node];
    int start = (node > 0) ? endoff[node - 1] : 0;

    float4 acc = g[(size_t)node * 32 + lane];   // self-loop term
    int e = start;
    for (; e + 4 <= end; e += 4) {
        int s0 = csr[e], s1 = csr[e + 1], s2 = csr[e + 2], s3 = csr[e + 3];
        float4 v0 = g[(size_t)s0 * 32 + lane];
        float4 v1 = g[(size_t)s1 * 32 + lane];
        float4 v2 = g[(size_t)s2 * 32 + lane];
        float4 v3 = g[(size_t)s3 * 32 + lane];
        acc.x += v0.x + v1.x + v2.x + v3.x;
        acc.y += v0.y + v1.y + v2.y + v3.y;
        acc.z += v0.z + v1.z + v2.z + v3.z;
        acc.w += v0.w + v1.w + v2.w + v3.w;
    }
    for (; e < end; e++) {
        int s = csr[e];
        float4 v = g[(size_t)s * 32 + lane];
        acc.x += v.x; acc.y += v.y; acc.z += v.z; acc.w += v.w;
    }

    float dv = dinv[node];
    float4 bb = ((const float4*)bias)[lane];
    acc.x = acc.x * dv + bb.x;
    acc.y = acc.y * dv + bb.y;
    acc.z = acc.z * dv + bb.z;
    acc.w = acc.w * dv + bb.w;
    if (do_relu) {
        acc.x = fmaxf(acc.x, 0.f); acc.y = fmaxf(acc.y, 0.f);
        acc.z = fmaxf(acc.z, 0.f); acc.w = fmaxf(acc.w, 0.f);
    }
    out[(size_t)node * 32 + lane] = acc;
}

// ---------------------------------------------------------------------------
extern "C" void kernel_launch(void* const* d_in, const int* in_sizes, int n_in,
                              void* d_out, int out_size) {
    const float* x  = (const float*)d_in[0];
    const void*  ei = (const void*) d_in[1];
    const float* W1 = (const float*)d_in[2];
    const float* b1 = (const float*)d_in[3];
    const float* W2 = (const float*)d_in[4];
    const float* b2 = (const float*)d_in[5];
    float* out = (float*)d_out;

    int n = in_sizes[0] / D;
    int E = in_sizes[1] / 2;

    float *dinv, *gbuf, *h1;
    int *cnt, *off, *bsum, *csr;
    cudaGetSymbolAddress((void**)&dinv, g_dinv);
    cudaGetSymbolAddress((void**)&gbuf, g_gbuf);
    cudaGetSymbolAddress((void**)&h1,   g_h1);
    cudaGetSymbolAddress((void**)&cnt,  g_cnt);
    cudaGetSymbolAddress((void**)&off,  g_off);
    cudaGetSymbolAddress((void**)&bsum, g_bsum);
    cudaGetSymbolAddress((void**)&csr,  g_csr);

    int nb_node = (n + 255) / 256;
    int nb_edge = (E + 255) / 256;
    int nb_scan = (n + SCAN_BLK - 1) / SCAN_BLK;

    detect_kernel<<<1, 32>>>((const long long*)ei, E, n);

    // CSR build + dinv
    zero_cnt_kernel<<<nb_node, 256>>>(cnt, n);
    hist_kernel<<<nb_edge, 256>>>(ei, cnt, E);
    dinv_kernel<<<nb_node, 256>>>(cnt, dinv, n);
    scan1_kernel<<<nb_scan, SCAN_BLK>>>(cnt, off, bsum, n);
    scan2_kernel<<<1, SCAN_BLK>>>(bsum, nb_scan);
    scan3_kernel<<<nb_scan, SCAN_BLK>>>(off, bsum, n);
    fill_kernel<<<nb_edge, 256>>>(ei, off, csr, E);

    int gemm_blocks = (n + 127) / 128;
    long long gt = (long long)n * 32;
    int gather_blocks = (int)((gt + 255) / 256);

    // Layer 1
    gemm_kernel<<<gemm_blocks, 256>>>(x, W1, dinv, gbuf, n);
    gather_kernel<<<gather_blocks, 256>>>(csr, off, (const float4*)gbuf, dinv, b1,
                                          (float4*)h1, n, 1);
    // Layer 2
    gemm_kernel<<<gemm_blocks, 256>>>(h1, W2, dinv, gbuf, n);
    gather_kernel<<<gather_blocks, 256>>>(csr, off, (const float4*)gbuf, dinv, b2,
                                          (float4*)out, n, 0);
}

// round 5
// speedup vs baseline: 2.1711x; 1.0447x over previous
#include <cuda_runtime.h>
#include <cuda_bf16.h>
#include <cstdint>

using u32 = unsigned int;
using u64 = unsigned long long;

#define D 128
#define MAXN 50048
#define MAXE 800000
#define SCAN_BLK 256
#define NB_SCAN ((MAXN + SCAN_BLK - 1) / SCAN_BLK)

// ---------------------------------------------------------------------------
// Scratch (device globals: no allocation allowed)
__device__ float g_dinv[MAXN];
__device__ float g_gbuf[(size_t)MAXN * D];
__device__ float g_h1[(size_t)MAXN * D];
__device__ int   g_cnt[MAXN];
__device__ int   g_off[MAXN];
__device__ int   g_bsum[NB_SCAN];
__device__ int   g_csr[MAXE];
__device__ int   g_is32;
// Pre-transposed, bf16-split weights: Wt[n][k] = W[k][n], row-major [128][128]
__device__ unsigned short g_w1h[128 * 128];
__device__ unsigned short g_w1l[128 * 128];
__device__ unsigned short g_w2h[128 * 128];
__device__ unsigned short g_w2l[128 * 128];

// ---------------------------------------------------------------------------
__global__ void detect_kernel(const long long* __restrict__ ei, int E, int n) {
    if (threadIdx.x == 0) {
        int is32 = 0;
        int m = E < 64 ? E : 64;
        for (int i = 0; i < m; i++) {
            long long v = ei[i];
            if (v < 0 || v >= (long long)n) { is32 = 1; break; }
        }
        g_is32 = is32;
    }
}

__device__ __forceinline__ int load_idx(const void* ei, size_t pos) {
    if (g_is32) return ((const int*)ei)[pos];
    return (int)((const long long*)ei)[pos];
}

// ---------------------------------------------------------------------------
// Transpose + bf16-split both weights: Wt[n][k] hi/lo.
__global__ void prep_w_kernel(const float* __restrict__ W1,
                              const float* __restrict__ W2,
                              unsigned short* w1h, unsigned short* w1l,
                              unsigned short* w2h, unsigned short* w2l) {
    int i = blockIdx.x * blockDim.x + threadIdx.x;
    if (i >= 2 * 128 * 128) return;
    int which = i >> 14;
    int j = i & 16383;
    int k = j >> 7, nn = j & 127;
    const float* W = which ? W2 : W1;
    float v = W[k * 128 + nn];
    __nv_bfloat16 hb = __float2bfloat16(v);
    float hf = __bfloat162float(hb);
    __nv_bfloat16 lb = __float2bfloat16(v - hf);
    int off = nn * 128 + k;
    unsigned short* dh = which ? w2h : w1h;
    unsigned short* dl = which ? w2l : w1l;
    dh[off] = __bfloat16_as_ushort(hb);
    dl[off] = __bfloat16_as_ushort(lb);
}

// ---------------------------------------------------------------------------
__global__ void zero_cnt_kernel(int* cnt, int n) {
    int i = blockIdx.x * blockDim.x + threadIdx.x;
    if (i < n) cnt[i] = 0;
}

__global__ void hist_kernel(const void* __restrict__ ei, int* cnt, int E) {
    int e = blockIdx.x * blockDim.x + threadIdx.x;
    if (e < E) atomicAdd(&cnt[load_idx(ei, (size_t)E + e)], 1);
}

__global__ void dinv_kernel(const int* __restrict__ cnt, float* dinv, int n) {
    int i = blockIdx.x * blockDim.x + threadIdx.x;
    if (i < n) dinv[i] = rsqrtf((float)cnt[i] + 1.0f);
}

__global__ void scan1_kernel(const int* __restrict__ cnt, int* off, int* bsum, int n) {
    __shared__ int s[SCAN_BLK];
    int i = blockIdx.x * SCAN_BLK + threadIdx.x;
    int v = (i < n) ? cnt[i] : 0;
    s[threadIdx.x] = v;
    __syncthreads();
#pragma unroll
    for (int d = 1; d < SCAN_BLK; d <<= 1) {
        int t = (threadIdx.x >= d) ? s[threadIdx.x - d] : 0;
        __syncthreads();
        s[threadIdx.x] += t;
        __syncthreads();
    }
    if (i < n) off[i] = s[threadIdx.x] - v;
    if (threadIdx.x == SCAN_BLK - 1) bsum[blockIdx.x] = s[SCAN_BLK - 1];
}

__global__ void scan2_kernel(int* bsum, int nb) {
    __shared__ int s[SCAN_BLK];
    int v = (threadIdx.x < nb) ? bsum[threadIdx.x] : 0;
    s[threadIdx.x] = v;
    __syncthreads();
#pragma unroll
    for (int d = 1; d < SCAN_BLK; d <<= 1) {
        int t = (threadIdx.x >= d) ? s[threadIdx.x - d] : 0;
        __syncthreads();
        s[threadIdx.x] += t;
        __syncthreads();
    }
    if (threadIdx.x < nb) bsum[threadIdx.x] = s[threadIdx.x] - v;
}

__global__ void scan3_kernel(int* off, const int* __restrict__ bsum, int n) {
    int i = blockIdx.x * SCAN_BLK + threadIdx.x;
    if (i < n) off[i] += bsum[blockIdx.x];
}

__global__ void fill_kernel(const void* __restrict__ ei, int* off, int* csr, int E) {
    int e = blockIdx.x * blockDim.x + threadIdx.x;
    if (e < E) {
        int s = load_idx(ei, (size_t)e);
        int d = load_idx(ei, (size_t)E + e);
        int pos = atomicAdd(&off[d], 1);
        csr[pos] = s;
    }
}

// ---------------------------------------------------------------------------
// bf16-split GEMM via mma.sync (HMMA): g[row] = (X[row] @ W) * dinv[row]
// acc(fp32) = Ah@Bh + Ah@Bl + Al@Bh  (residual ~2^-16)
// CTA: 256 thr / 8 warps, tile 128x128. Warp w owns rows w*16..w*16+15, all 128 cols.

#define SA 136                      // smem row stride (bf16 elems), 272 B
#define SM_AH 0
#define SM_AL (128 * SA * 2)
#define SM_WH (2 * 128 * SA * 2)
#define SM_WL (3 * 128 * SA * 2)
#define SM_TOTAL (4 * 128 * SA * 2)

__device__ __forceinline__ u32 smem_u32(const void* p) {
    u32 a;
    asm("{ .reg .u64 t; cvta.to.shared.u64 t, %1; cvt.u32.u64 %0, t; }" : "=r"(a) : "l"(p));
    return a;
}

__device__ __forceinline__ void ldsm4(u32& r0, u32& r1, u32& r2, u32& r3, u32 addr) {
    asm volatile("ldmatrix.sync.aligned.m8n8.x4.shared.b16 {%0,%1,%2,%3}, [%4];"
                 : "=r"(r0), "=r"(r1), "=r"(r2), "=r"(r3) : "r"(addr));
}

__device__ __forceinline__ void mma16816(float* c, u32 a0, u32 a1, u32 a2, u32 a3,
                                         u32 b0, u32 b1) {
    asm volatile(
        "mma.sync.aligned.m16n8k16.row.col.f32.bf16.bf16.f32 "
        "{%0,%1,%2,%3}, {%4,%5,%6,%7}, {%8,%9}, {%0,%1,%2,%3};"
        : "+f"(c[0]), "+f"(c[1]), "+f"(c[2]), "+f"(c[3])
        : "r"(a0), "r"(a1), "r"(a2), "r"(a3), "r"(b0), "r"(b1));
}

__global__ __launch_bounds__(256) void gemm_mma_kernel(const float* __restrict__ X,
                                                       const unsigned short* __restrict__ Wh,
                                                       const unsigned short* __restrict__ Wl,
                                                       const float* __restrict__ dinv,
                                                       float* __restrict__ g, int n) {
    extern __shared__ char smem[];
    int tid = threadIdx.x;
    int wid = tid >> 5;
    int lane = tid & 31;
    int row0 = blockIdx.x * 128;

    // ---- stage W hi/lo into smem (re-stride 128 -> SA) ----
    {
        // 128 rows x 32 float4(=8 bf16) each: 4096 float4 per tile
        const uint4* sh = (const uint4*)Wh;
        const uint4* sl = (const uint4*)Wl;
        for (int i = tid; i < 128 * 16; i += 256) {
            int r = i >> 4, c = i & 15;          // c: 16 x uint4 (8 bf16 each)
            uint4 vh = sh[r * 16 + c];
            uint4 vl = sl[r * 16 + c];
            *(uint4*)(smem + SM_WH + (r * SA + c * 8) * 2) = vh;
            *(uint4*)(smem + SM_WL + (r * SA + c * 8) * 2) = vl;
        }
    }
    // ---- load X tile, split to bf16 hi/lo ----
    {
        int r = tid >> 1;
        int half = tid & 1;
        int row = row0 + r;
#pragma unroll
        for (int j = 0; j < 16; j++) {
            float4 v = (row < n)
                ? __ldg((const float4*)(X + (size_t)row * D + half * 64) + j)
                : make_float4(0.f, 0.f, 0.f, 0.f);
            float f[4] = {v.x, v.y, v.z, v.w};
            unsigned short hs[4], ls[4];
#pragma unroll
            for (int p = 0; p < 4; p++) {
                __nv_bfloat16 hb = __float2bfloat16(f[p]);
                __nv_bfloat16 lb = __float2bfloat16(f[p] - __bfloat162float(hb));
                hs[p] = __bfloat16_as_ushort(hb);
                ls[p] = __bfloat16_as_ushort(lb);
            }
            int col = half * 64 + j * 4;
            uint2 hw = make_uint2((u32)hs[0] | ((u32)hs[1] << 16),
                                  (u32)hs[2] | ((u32)hs[3] << 16));
            uint2 lw = make_uint2((u32)ls[0] | ((u32)ls[1] << 16),
                                  (u32)ls[2] | ((u32)ls[3] << 16));
            *(uint2*)(smem + SM_AH + (r * SA + col) * 2) = hw;
            *(uint2*)(smem + SM_AL + (r * SA + col) * 2) = lw;
        }
    }
    __syncthreads();

    // ---- mma mainloop ----
    float acc[16][4];
#pragma unroll
    for (int i = 0; i < 16; i++)
#pragma unroll
        for (int j = 0; j < 4; j++) acc[i][j] = 0.f;

    u32 sbase = smem_u32(smem);
    int gq = lane >> 3;          // ldmatrix group 0..3
    int gr = lane & 7;

    // A frag lane address offset (within tile): m = w*16 + (g&1)*8 + r ; k = (g>>1)*8
    u32 a_lane_off = (u32)(((wid * 16 + (gq & 1) * 8 + gr) * SA + (gq >> 1) * 8) * 2);
    // B frag lane address offset: n = (g>>1)*8 + r ; k = (g&1)*8
    u32 b_lane_off = (u32)((((gq >> 1) * 8 + gr) * SA + (gq & 1) * 8) * 2);

#pragma unroll
    for (int pass = 0; pass < 3; pass++) {
        u32 abase = sbase + (pass == 2 ? SM_AL : SM_AH) + a_lane_off;
        u32 bbase = sbase + (pass == 1 ? SM_WL : SM_WH) + b_lane_off;
#pragma unroll
        for (int kt = 0; kt < 8; kt++) {
            u32 a0, a1, a2, a3;
            ldsm4(a0, a1, a2, a3, abase + kt * 32);
#pragma unroll
            for (int np = 0; np < 8; np++) {
                u32 b0, b1, b2, b3;
                ldsm4(b0, b1, b2, b3, bbase + kt * 32 + np * (16 * SA * 2));
                mma16816(acc[np * 2 + 0], a0, a1, a2, a3, b0, b1);
                mma16816(acc[np * 2 + 1], a0, a1, a2, a3, b2, b3);
            }
        }
    }

    // ---- epilogue ----
    {
        int q = lane >> 2, p = lane & 3;
        int m0 = row0 + wid * 16 + q;
        int m1 = m0 + 8;
        float dv0 = (m0 < n) ? dinv[m0] : 0.f;
        float dv1 = (m1 < n) ? dinv[m1] : 0.f;
#pragma unroll
        for (int nt = 0; nt < 16; nt++) {
            int col = nt * 8 + p * 2;
            if (m0 < n)
                *(float2*)(g + (size_t)m0 * D + col) =
                    make_float2(acc[nt][0] * dv0, acc[nt][1] * dv0);
            if (m1 < n)
                *(float2*)(g + (size_t)m1 * D + col) =
                    make_float2(acc[nt][2] * dv1, acc[nt][3] * dv1);
        }
    }
}

// ---------------------------------------------------------------------------
// Pull aggregation: warp per node. out[j] = dinv[j]*(sum_{i->j} g[i] + g[j]) + b
__global__ void gather_kernel(const int* __restrict__ csr,
                              const int* __restrict__ endoff,
                              const float4* __restrict__ g,
                              const float* __restrict__ dinv,
                              const float* __restrict__ bias,
                              float4* __restrict__ out, int n, int do_relu) {
    int gt = blockIdx.x * blockDim.x + threadIdx.x;
    int node = gt >> 5;
    int lane = gt & 31;
    if (node >= n) return;

    int end = endoff[node];
    int start = (node > 0) ? endoff[node - 1] : 0;

    float4 acc = g[(size_t)node * 32 + lane];
    int e = start;
    for (; e + 4 <= end; e += 4) {
        int s0 = csr[e], s1 = csr[e + 1], s2 = csr[e + 2], s3 = csr[e + 3];
        float4 v0 = g[(size_t)s0 * 32 + lane];
        float4 v1 = g[(size_t)s1 * 32 + lane];
        float4 v2 = g[(size_t)s2 * 32 + lane];
        float4 v3 = g[(size_t)s3 * 32 + lane];
        acc.x += v0.x + v1.x + v2.x + v3.x;
        acc.y += v0.y + v1.y + v2.y + v3.y;
        acc.z += v0.z + v1.z + v2.z + v3.z;
        acc.w += v0.w + v1.w + v2.w + v3.w;
    }
    for (; e < end; e++) {
        int s = csr[e];
        float4 v = g[(size_t)s * 32 + lane];
        acc.x += v.x; acc.y += v.y; acc.z += v.z; acc.w += v.w;
    }

    float dv = dinv[node];
    float4 bb = ((const float4*)bias)[lane];
    acc.x = acc.x * dv + bb.x;
    acc.y = acc.y * dv + bb.y;
    acc.z = acc.z * dv + bb.z;
    acc.w = acc.w * dv + bb.w;
    if (do_relu) {
        acc.x = fmaxf(acc.x, 0.f); acc.y = fmaxf(acc.y, 0.f);
        acc.z = fmaxf(acc.z, 0.f); acc.w = fmaxf(acc.w, 0.f);
    }
    out[(size_t)node * 32 + lane] = acc;
}

// ---------------------------------------------------------------------------
extern "C" void kernel_launch(void* const* d_in, const int* in_sizes, int n_in,
                              void* d_out, int out_size) {
    const float* x  = (const float*)d_in[0];
    const void*  ei = (const void*) d_in[1];
    const float* W1 = (const float*)d_in[2];
    const float* b1 = (const float*)d_in[3];
    const float* W2 = (const float*)d_in[4];
    const float* b2 = (const float*)d_in[5];
    float* out = (float*)d_out;

    int n = in_sizes[0] / D;
    int E = in_sizes[1] / 2;

    float *dinv, *gbuf, *h1;
    int *cnt, *off, *bsum, *csr;
    unsigned short *w1h, *w1l, *w2h, *w2l;
    cudaGetSymbolAddress((void**)&dinv, g_dinv);
    cudaGetSymbolAddress((void**)&gbuf, g_gbuf);
    cudaGetSymbolAddress((void**)&h1,   g_h1);
    cudaGetSymbolAddress((void**)&cnt,  g_cnt);
    cudaGetSymbolAddress((void**)&off,  g_off);
    cudaGetSymbolAddress((void**)&bsum, g_bsum);
    cudaGetSymbolAddress((void**)&csr,  g_csr);
    cudaGetSymbolAddress((void**)&w1h,  g_w1h);
    cudaGetSymbolAddress((void**)&w1l,  g_w1l);
    cudaGetSymbolAddress((void**)&w2h,  g_w2h);
    cudaGetSymbolAddress((void**)&w2l,  g_w2l);

    static int smem_set = 0;
    if (!smem_set) {
        cudaFuncSetAttribute(gemm_mma_kernel,
                             cudaFuncAttributeMaxDynamicSharedMemorySize, SM_TOTAL);
        smem_set = 1;
    }

    int nb_node = (n + 255) / 256;
    int nb_edge = (E + 255) / 256;
    int nb_scan = (n + SCAN_BLK - 1) / SCAN_BLK;

    detect_kernel<<<1, 32>>>((const long long*)ei, E, n);
    prep_w_kernel<<<(2 * 128 * 128 + 255) / 256, 256>>>(W1, W2, w1h, w1l, w2h, w2l);

    zero_cnt_kernel<<<nb_node, 256>>>(cnt, n);
    hist_kernel<<<nb_edge, 256>>>(ei, cnt, E);
    dinv_kernel<<<nb_node, 256>>>(cnt, dinv, n);
    scan1_kernel<<<nb_scan, SCAN_BLK>>>(cnt, off, bsum, n);
    scan2_kernel<<<1, SCAN_BLK>>>(bsum, nb_scan);
    scan3_kernel<<<nb_scan, SCAN_BLK>>>(off, bsum, n);
    fill_kernel<<<nb_edge, 256>>>(ei, off, csr, E);

    int gemm_blocks = (n + 127) / 128;
    long long gt = (long long)n * 32;
    int gather_blocks = (int)((gt + 255) / 256);

    // Layer 1
    gemm_mma_kernel<<<gemm_blocks, 256, SM_TOTAL>>>(x, w1h, w1l, dinv, gbuf, n);
    gather_kernel<<<gather_blocks, 256>>>(csr, off, (const float4*)gbuf, dinv, b1,
                                          (float4*)h1, n, 1);
    // Layer 2
    gemm_mma_kernel<<<gemm_blocks, 256, SM_TOTAL>>>(h1, w2h, w2l, dinv, gbuf, n);
    gather_kernel<<<gather_blocks, 256>>>(csr, off, (const float4*)gbuf, dinv, b2,
                                          (float4*)out, n, 0);
}

// round 6
// speedup vs baseline: 2.2402x; 1.0318x over previous
#include <cuda_runtime.h>
#include <cuda_bf16.h>
#include <cstdint>

using u32 = unsigned int;
using u64 = unsigned long long;

#define D 128
#define MAXN 50048
#define MAXE 800000
#define SCAN_BLK 256
#define NB_SCAN ((MAXN + SCAN_BLK - 1) / SCAN_BLK)

// ---------------------------------------------------------------------------
// Scratch (device globals: no allocation allowed)
__device__ float g_dinv[MAXN];
__device__ float g_gbuf[(size_t)MAXN * D];
__device__ float g_h1[(size_t)MAXN * D];
__device__ int   g_cnt[MAXN];
__device__ int   g_off[MAXN];
__device__ int   g_bsum[NB_SCAN];
__device__ int   g_csr[MAXE];
__device__ int   g_is32;
// Pre-transposed, bf16-split weights: Wt[n][k] = W[k][n], row-major [128][128]
__device__ unsigned short g_w1h[128 * 128];
__device__ unsigned short g_w1l[128 * 128];
__device__ unsigned short g_w2h[128 * 128];
__device__ unsigned short g_w2l[128 * 128];

__device__ __forceinline__ int load_idx(const void* ei, size_t pos) {
    if (g_is32) return ((const int*)ei)[pos];
    return (int)((const long long*)ei)[pos];
}

// packed fp32x2 add (sm_100+ baseline PTX)
#define ADD2(o, a, b) asm("add.rn.f32x2 %0, %1, %2;" : "=l"(o) : "l"(a), "l"(b))

// ---------------------------------------------------------------------------
// Fused: edge-dtype detect + cnt zero + weight transpose/bf16-split.
__global__ void prep_all_kernel(const float* __restrict__ W1,
                                const float* __restrict__ W2,
                                unsigned short* w1h, unsigned short* w1l,
                                unsigned short* w2h, unsigned short* w2l,
                                const long long* __restrict__ ei, int E,
                                int* cnt, int n) {
    int i = blockIdx.x * blockDim.x + threadIdx.x;
    if (i == 0) {
        int is32 = 0;
        int m = E < 64 ? E : 64;
        for (int t = 0; t < m; t++) {
            long long v = ei[t];
            if (v < 0 || v >= (long long)n) { is32 = 1; break; }
        }
        g_is32 = is32;
    }
    if (i < n) cnt[i] = 0;
    if (i < 2 * 128 * 128) {
        int which = i >> 14;
        int j = i & 16383;
        int k = j >> 7, nn = j & 127;
        const float* W = which ? W2 : W1;
        float v = W[k * 128 + nn];
        __nv_bfloat16 hb = __float2bfloat16(v);
        __nv_bfloat16 lb = __float2bfloat16(v - __bfloat162float(hb));
        int off = nn * 128 + k;
        (which ? w2h : w1h)[off] = __bfloat16_as_ushort(hb);
        (which ? w2l : w1l)[off] = __bfloat16_as_ushort(lb);
    }
}

// ---------------------------------------------------------------------------
__global__ void hist_kernel(const void* __restrict__ ei, int* cnt, int E) {
    int e = blockIdx.x * blockDim.x + threadIdx.x;
    if (e < E) atomicAdd(&cnt[load_idx(ei, (size_t)E + e)], 1);
}

// Block-local exclusive scan over cnt -> off; per-block sums -> bsum; also dinv.
__global__ void scan1_kernel(const int* __restrict__ cnt, int* off, int* bsum,
                             float* dinv, int n) {
    __shared__ int s[SCAN_BLK];
    int i = blockIdx.x * SCAN_BLK + threadIdx.x;
    int v = (i < n) ? cnt[i] : 0;
    if (i < n) dinv[i] = rsqrtf((float)v + 1.0f);   // +1 self-loop
    s[threadIdx.x] = v;
    __syncthreads();
#pragma unroll
    for (int d = 1; d < SCAN_BLK; d <<= 1) {
        int t = (threadIdx.x >= d) ? s[threadIdx.x - d] : 0;
        __syncthreads();
        s[threadIdx.x] += t;
        __syncthreads();
    }
    if (i < n) off[i] = s[threadIdx.x] - v;        // block-local exclusive
    if (threadIdx.x == SCAN_BLK - 1) bsum[blockIdx.x] = s[SCAN_BLK - 1];
}

__global__ void scan2_kernel(int* bsum, int nb) {
    __shared__ int s[SCAN_BLK];
    int v = (threadIdx.x < nb) ? bsum[threadIdx.x] : 0;
    s[threadIdx.x] = v;
    __syncthreads();
#pragma unroll
    for (int d = 1; d < SCAN_BLK; d <<= 1) {
        int t = (threadIdx.x >= d) ? s[threadIdx.x - d] : 0;
        __syncthreads();
        s[threadIdx.x] += t;
        __syncthreads();
    }
    if (threadIdx.x < nb) bsum[threadIdx.x] = s[threadIdx.x] - v;  // exclusive
}

// fill CSR: global pos = local cursor + bsum[block of d]
__global__ void fill_kernel(const void* __restrict__ ei, int* off,
                            const int* __restrict__ bsum, int* csr, int E) {
    int e = blockIdx.x * blockDim.x + threadIdx.x;
    if (e < E) {
        int s = load_idx(ei, (size_t)e);
        int d = load_idx(ei, (size_t)E + e);
        int pos = atomicAdd(&off[d], 1) + bsum[d >> 8];
        csr[pos] = s;
    }
}

// ---------------------------------------------------------------------------
// bf16-split GEMM via mma.sync (HMMA): g[row] = (X[row] @ W) * dinv[row]
#define SA 136
#define SM_AH 0
#define SM_AL (128 * SA * 2)
#define SM_WH (2 * 128 * SA * 2)
#define SM_WL (3 * 128 * SA * 2)
#define SM_TOTAL (4 * 128 * SA * 2)

__device__ __forceinline__ u32 smem_u32(const void* p) {
    u32 a;
    asm("{ .reg .u64 t; cvta.to.shared.u64 t, %1; cvt.u32.u64 %0, t; }" : "=r"(a) : "l"(p));
    return a;
}

__device__ __forceinline__ void ldsm4(u32& r0, u32& r1, u32& r2, u32& r3, u32 addr) {
    asm volatile("ldmatrix.sync.aligned.m8n8.x4.shared.b16 {%0,%1,%2,%3}, [%4];"
                 : "=r"(r0), "=r"(r1), "=r"(r2), "=r"(r3) : "r"(addr));
}

__device__ __forceinline__ void mma16816(float* c, u32 a0, u32 a1, u32 a2, u32 a3,
                                         u32 b0, u32 b1) {
    asm volatile(
        "mma.sync.aligned.m16n8k16.row.col.f32.bf16.bf16.f32 "
        "{%0,%1,%2,%3}, {%4,%5,%6,%7}, {%8,%9}, {%0,%1,%2,%3};"
        : "+f"(c[0]), "+f"(c[1]), "+f"(c[2]), "+f"(c[3])
        : "r"(a0), "r"(a1), "r"(a2), "r"(a3), "r"(b0), "r"(b1));
}

__global__ __launch_bounds__(256) void gemm_mma_kernel(const float* __restrict__ X,
                                                       const unsigned short* __restrict__ Wh,
                                                       const unsigned short* __restrict__ Wl,
                                                       const float* __restrict__ dinv,
                                                       float* __restrict__ g, int n) {
    extern __shared__ char smem[];
    int tid = threadIdx.x;
    int wid = tid >> 5;
    int lane = tid & 31;
    int row0 = blockIdx.x * 128;

    {
        const uint4* sh = (const uint4*)Wh;
        const uint4* sl = (const uint4*)Wl;
        for (int i = tid; i < 128 * 16; i += 256) {
            int r = i >> 4, c = i & 15;
            uint4 vh = sh[r * 16 + c];
            uint4 vl = sl[r * 16 + c];
            *(uint4*)(smem + SM_WH + (r * SA + c * 8) * 2) = vh;
            *(uint4*)(smem + SM_WL + (r * SA + c * 8) * 2) = vl;
        }
    }
    {
        int r = tid >> 1;
        int half = tid & 1;
        int row = row0 + r;
#pragma unroll
        for (int j = 0; j < 16; j++) {
            float4 v = (row < n)
                ? __ldg((const float4*)(X + (size_t)row * D + half * 64) + j)
                : make_float4(0.f, 0.f, 0.f, 0.f);
            float f[4] = {v.x, v.y, v.z, v.w};
            unsigned short hs[4], ls[4];
#pragma unroll
            for (int p = 0; p < 4; p++) {
                __nv_bfloat16 hb = __float2bfloat16(f[p]);
                __nv_bfloat16 lb = __float2bfloat16(f[p] - __bfloat162float(hb));
                hs[p] = __bfloat16_as_ushort(hb);
                ls[p] = __bfloat16_as_ushort(lb);
            }
            int col = half * 64 + j * 4;
            uint2 hw = make_uint2((u32)hs[0] | ((u32)hs[1] << 16),
                                  (u32)hs[2] | ((u32)hs[3] << 16));
            uint2 lw = make_uint2((u32)ls[0] | ((u32)ls[1] << 16),
                                  (u32)ls[2] | ((u32)ls[3] << 16));
            *(uint2*)(smem + SM_AH + (r * SA + col) * 2) = hw;
            *(uint2*)(smem + SM_AL + (r * SA + col) * 2) = lw;
        }
    }
    __syncthreads();

    float acc[16][4];
#pragma unroll
    for (int i = 0; i < 16; i++)
#pragma unroll
        for (int j = 0; j < 4; j++) acc[i][j] = 0.f;

    u32 sbase = smem_u32(smem);
    int gq = lane >> 3;
    int gr = lane & 7;
    u32 a_lane_off = (u32)(((wid * 16 + (gq & 1) * 8 + gr) * SA + (gq >> 1) * 8) * 2);
    u32 b_lane_off = (u32)((((gq >> 1) * 8 + gr) * SA + (gq & 1) * 8) * 2);

#pragma unroll
    for (int pass = 0; pass < 3; pass++) {
        u32 abase = sbase + (pass == 2 ? SM_AL : SM_AH) + a_lane_off;
        u32 bbase = sbase + (pass == 1 ? SM_WL : SM_WH) + b_lane_off;
#pragma unroll
        for (int kt = 0; kt < 8; kt++) {
            u32 a0, a1, a2, a3;
            ldsm4(a0, a1, a2, a3, abase + kt * 32);
#pragma unroll
            for (int np = 0; np < 8; np++) {
                u32 b0, b1, b2, b3;
                ldsm4(b0, b1, b2, b3, bbase + kt * 32 + np * (16 * SA * 2));
                mma16816(acc[np * 2 + 0], a0, a1, a2, a3, b0, b1);
                mma16816(acc[np * 2 + 1], a0, a1, a2, a3, b2, b3);
            }
        }
    }

    {
        int q = lane >> 2, p = lane & 3;
        int m0 = row0 + wid * 16 + q;
        int m1 = m0 + 8;
        float dv0 = (m0 < n) ? dinv[m0] : 0.f;
        float dv1 = (m1 < n) ? dinv[m1] : 0.f;
#pragma unroll
        for (int nt = 0; nt < 16; nt++) {
            int col = nt * 8 + p * 2;
            if (m0 < n)
                *(float2*)(g + (size_t)m0 * D + col) =
                    make_float2(acc[nt][0] * dv0, acc[nt][1] * dv0);
            if (m1 < n)
                *(float2*)(g + (size_t)m1 * D + col) =
                    make_float2(acc[nt][2] * dv1, acc[nt][3] * dv1);
        }
    }
}

// ---------------------------------------------------------------------------
// Pull aggregation, f32x2-packed accumulate. Warp per node, lane owns 16B.
// end = off[j]+bsum[j>>8] (off is post-fill cursor = local inclusive end).
__global__ void gather_kernel(const int* __restrict__ csr,
                              const int* __restrict__ off,
                              const int* __restrict__ bsum,
                              const ulonglong2* __restrict__ g,
                              const float* __restrict__ dinv,
                              const float* __restrict__ bias,
                              float4* __restrict__ out, int n, int do_relu) {
    int gt = blockIdx.x * blockDim.x + threadIdx.x;
    int node = gt >> 5;
    int lane = gt & 31;
    if (node >= n) return;

    int end = off[node] + bsum[node >> 8];
    int start = (node > 0) ? (off[node - 1] + bsum[(node - 1) >> 8]) : 0;

    ulonglong2 s = g[(size_t)node * 32 + lane];   // self-loop term
    u64 ax = s.x, ay = s.y;

    int e = start;
    for (; e + 4 <= end; e += 4) {
        int s0 = csr[e], s1 = csr[e + 1], s2 = csr[e + 2], s3 = csr[e + 3];
        ulonglong2 v0 = g[(size_t)s0 * 32 + lane];
        ulonglong2 v1 = g[(size_t)s1 * 32 + lane];
        ulonglong2 v2 = g[(size_t)s2 * 32 + lane];
        ulonglong2 v3 = g[(size_t)s3 * 32 + lane];
        u64 t0, t1;
        ADD2(t0, v0.x, v1.x); ADD2(t1, v2.x, v3.x);
        ADD2(ax, ax, t0);     ADD2(ax, ax, t1);
        ADD2(t0, v0.y, v1.y); ADD2(t1, v2.y, v3.y);
        ADD2(ay, ay, t0);     ADD2(ay, ay, t1);
    }
    for (; e < end; e++) {
        int s2 = csr[e];
        ulonglong2 v = g[(size_t)s2 * 32 + lane];
        ADD2(ax, ax, v.x);
        ADD2(ay, ay, v.y);
    }

    u32 x0, x1, y0, y1;
    asm("mov.b64 {%0,%1}, %2;" : "=r"(x0), "=r"(x1) : "l"(ax));
    asm("mov.b64 {%0,%1}, %2;" : "=r"(y0), "=r"(y1) : "l"(ay));

    float dv = dinv[node];
    float4 bb = ((const float4*)bias)[lane];
    float4 o;
    o.x = __uint_as_float(x0) * dv + bb.x;
    o.y = __uint_as_float(x1) * dv + bb.y;
    o.z = __uint_as_float(y0) * dv + bb.z;
    o.w = __uint_as_float(y1) * dv + bb.w;
    if (do_relu) {
        o.x = fmaxf(o.x, 0.f); o.y = fmaxf(o.y, 0.f);
        o.z = fmaxf(o.z, 0.f); o.w = fmaxf(o.w, 0.f);
    }
    out[(size_t)node * 32 + lane] = o;
}

// ---------------------------------------------------------------------------
extern "C" void kernel_launch(void* const* d_in, const int* in_sizes, int n_in,
                              void* d_out, int out_size) {
    const float* x  = (const float*)d_in[0];
    const void*  ei = (const void*) d_in[1];
    const float* W1 = (const float*)d_in[2];
    const float* b1 = (const float*)d_in[3];
    const float* W2 = (const float*)d_in[4];
    const float* b2 = (const float*)d_in[5];
    float* out = (float*)d_out;

    int n = in_sizes[0] / D;
    int E = in_sizes[1] / 2;

    float *dinv, *gbuf, *h1;
    int *cnt, *off, *bsum, *csr;
    unsigned short *w1h, *w1l, *w2h, *w2l;
    cudaGetSymbolAddress((void**)&dinv, g_dinv);
    cudaGetSymbolAddress((void**)&gbuf, g_gbuf);
    cudaGetSymbolAddress((void**)&h1,   g_h1);
    cudaGetSymbolAddress((void**)&cnt,  g_cnt);
    cudaGetSymbolAddress((void**)&off,  g_off);
    cudaGetSymbolAddress((void**)&bsum, g_bsum);
    cudaGetSymbolAddress((void**)&csr,  g_csr);
    cudaGetSymbolAddress((void**)&w1h,  g_w1h);
    cudaGetSymbolAddress((void**)&w1l,  g_w1l);
    cudaGetSymbolAddress((void**)&w2h,  g_w2h);
    cudaGetSymbolAddress((void**)&w2l,  g_w2l);

    static int smem_set = 0;
    if (!smem_set) {
        cudaFuncSetAttribute(gemm_mma_kernel,
                             cudaFuncAttributeMaxDynamicSharedMemorySize, SM_TOTAL);
        smem_set = 1;
    }

    int prep_threads = (n > 2 * 128 * 128) ? n : 2 * 128 * 128;
    int nb_prep = (prep_threads + 255) / 256;
    int nb_edge = (E + 255) / 256;
    int nb_scan = (n + SCAN_BLK - 1) / SCAN_BLK;
    int gemm_blocks = (n + 127) / 128;
    long long gthreads = (long long)n * 32;
    int gather_blocks = (int)((gthreads + 255) / 256);

    // 0: prep (detect + zero cnt + weight split)
    prep_all_kernel<<<nb_prep, 256>>>(W1, W2, w1h, w1l, w2h, w2l,
                                      (const long long*)ei, E, cnt, n);
    // 1: histogram of dst
    hist_kernel<<<nb_edge, 256>>>(ei, cnt, E);
    // 2: block-local scan + dinv
    scan1_kernel<<<nb_scan, SCAN_BLK>>>(cnt, off, bsum, dinv, n);
    // 3: layer-1 GEMM (profiled slot)
    gemm_mma_kernel<<<gemm_blocks, 256, SM_TOTAL>>>(x, w1h, w1l, dinv, gbuf, n);
    // 4: scan of block sums
    scan2_kernel<<<1, SCAN_BLK>>>(bsum, nb_scan);
    // 5: CSR fill
    fill_kernel<<<nb_edge, 256>>>(ei, off, bsum, csr, E);
    // 6: layer-1 gather
    gather_kernel<<<gather_blocks, 256>>>(csr, off, bsum, (const ulonglong2*)gbuf,
                                          dinv, b1, (float4*)h1, n, 1);
    // 7: layer-2 GEMM
    gemm_mma_kernel<<<gemm_blocks, 256, SM_TOTAL>>>(h1, w2h, w2l, dinv, gbuf, n);
    // 8: layer-2 gather
    gather_kernel<<<gather_blocks, 256>>>(csr, off, bsum, (const ulonglong2*)gbuf,
                                          dinv, b2, (float4*)out, n, 0);
}

// round 7
// speedup vs baseline: 2.3508x; 1.0494x over previous
#include <cuda_runtime.h>
#include <cuda_bf16.h>
#include <cstdint>

using u32 = unsigned int;
using u64 = unsigned long long;

#define D 128
#define MAXN 50048
#define MAXE 800000
#define SCAN_BLK 256
#define NB_SCAN ((MAXN + SCAN_BLK - 1) / SCAN_BLK)

// ---------------------------------------------------------------------------
// Scratch (device globals: no allocation allowed)
__device__ float g_dinv[MAXN];
__device__ float g_gbuf[(size_t)MAXN * D];
__device__ float g_h1[(size_t)MAXN * D];
__device__ int   g_cnt[MAXN];
__device__ int   g_off[MAXN];
__device__ int   g_bsum[NB_SCAN];
__device__ int   g_csr[MAXE];
__device__ int   g_is32;
// Pre-transposed, bf16-split weights: Wt[n][k] = W[k][n], row-major [128][128]
__device__ unsigned short g_w1h[128 * 128];
__device__ unsigned short g_w1l[128 * 128];
__device__ unsigned short g_w2h[128 * 128];
__device__ unsigned short g_w2l[128 * 128];

__device__ __forceinline__ int load_idx(const void* ei, size_t pos) {
    if (g_is32) return ((const int*)ei)[pos];
    return (int)((const long long*)ei)[pos];
}

// packed fp32x2 add (sm_100+ baseline PTX)
#define ADD2(o, a, b) asm("add.rn.f32x2 %0, %1, %2;" : "=l"(o) : "l"(a), "l"(b))

// ---------------------------------------------------------------------------
// Fused: edge-dtype detect + cnt zero + weight transpose/bf16-split.
__global__ void prep_all_kernel(const float* __restrict__ W1,
                                const float* __restrict__ W2,
                                unsigned short* w1h, unsigned short* w1l,
                                unsigned short* w2h, unsigned short* w2l,
                                const long long* __restrict__ ei, int E,
                                int* cnt, int n) {
    int i = blockIdx.x * blockDim.x + threadIdx.x;
    if (i == 0) {
        int is32 = 0;
        int m = E < 64 ? E : 64;
        for (int t = 0; t < m; t++) {
            long long v = ei[t];
            if (v < 0 || v >= (long long)n) { is32 = 1; break; }
        }
        g_is32 = is32;
    }
    if (i < n) cnt[i] = 0;
    if (i < 2 * 128 * 128) {
        int which = i >> 14;
        int j = i & 16383;
        int k = j >> 7, nn = j & 127;
        const float* W = which ? W2 : W1;
        float v = W[k * 128 + nn];
        __nv_bfloat16 hb = __float2bfloat16(v);
        __nv_bfloat16 lb = __float2bfloat16(v - __bfloat162float(hb));
        int off = nn * 128 + k;
        (which ? w2h : w1h)[off] = __bfloat16_as_ushort(hb);
        (which ? w2l : w1l)[off] = __bfloat16_as_ushort(lb);
    }
}

// ---------------------------------------------------------------------------
__global__ void hist_kernel(const void* __restrict__ ei, int* cnt, int E) {
    int e = blockIdx.x * blockDim.x + threadIdx.x;
    if (e < E) atomicAdd(&cnt[load_idx(ei, (size_t)E + e)], 1);
}

// Block-local exclusive scan over cnt -> off; per-block sums -> bsum; also dinv.
__global__ void scan1_kernel(const int* __restrict__ cnt, int* off, int* bsum,
                             float* dinv, int n) {
    __shared__ int s[SCAN_BLK];
    int i = blockIdx.x * SCAN_BLK + threadIdx.x;
    int v = (i < n) ? cnt[i] : 0;
    if (i < n) dinv[i] = rsqrtf((float)v + 1.0f);   // +1 self-loop
    s[threadIdx.x] = v;
    __syncthreads();
#pragma unroll
    for (int d = 1; d < SCAN_BLK; d <<= 1) {
        int t = (threadIdx.x >= d) ? s[threadIdx.x - d] : 0;
        __syncthreads();
        s[threadIdx.x] += t;
        __syncthreads();
    }
    if (i < n) off[i] = s[threadIdx.x] - v;        // block-local exclusive
    if (threadIdx.x == SCAN_BLK - 1) bsum[blockIdx.x] = s[SCAN_BLK - 1];
}

__global__ void scan2_kernel(int* bsum, int nb) {
    __shared__ int s[SCAN_BLK];
    int v = (threadIdx.x < nb) ? bsum[threadIdx.x] : 0;
    s[threadIdx.x] = v;
    __syncthreads();
#pragma unroll
    for (int d = 1; d < SCAN_BLK; d <<= 1) {
        int t = (threadIdx.x >= d) ? s[threadIdx.x - d] : 0;
        __syncthreads();
        s[threadIdx.x] += t;
        __syncthreads();
    }
    if (threadIdx.x < nb) bsum[threadIdx.x] = s[threadIdx.x] - v;  // exclusive
}

// fill CSR: global pos = local cursor + bsum[block of d]
__global__ void fill_kernel(const void* __restrict__ ei, int* off,
                            const int* __restrict__ bsum, int* csr, int E) {
    int e = blockIdx.x * blockDim.x + threadIdx.x;
    if (e < E) {
        int s = load_idx(ei, (size_t)e);
        int d = load_idx(ei, (size_t)E + e);
        int pos = atomicAdd(&off[d], 1) + bsum[d >> 8];
        csr[pos] = s;
    }
}

// ---------------------------------------------------------------------------
// bf16-split GEMM via mma.sync (HMMA): g[row] = (X[row] @ W) * dinv[row]
// acc(fp32) = Ah@Bh + Ah@Bl + Al@Bh  (residual ~2^-16)
// CTA: 512 thr / 16 warps in 4x4 grid; warp owns 32 rows x 32 cols (acc 32 regs).
#define SA 136
#define SM_AH 0
#define SM_AL (128 * SA * 2)
#define SM_WH (2 * 128 * SA * 2)
#define SM_WL (3 * 128 * SA * 2)
#define SM_TOTAL (4 * 128 * SA * 2)

__device__ __forceinline__ u32 smem_u32(const void* p) {
    u32 a;
    asm("{ .reg .u64 t; cvta.to.shared.u64 t, %1; cvt.u32.u64 %0, t; }" : "=r"(a) : "l"(p));
    return a;
}

__device__ __forceinline__ void ldsm4(u32& r0, u32& r1, u32& r2, u32& r3, u32 addr) {
    asm volatile("ldmatrix.sync.aligned.m8n8.x4.shared.b16 {%0,%1,%2,%3}, [%4];"
                 : "=r"(r0), "=r"(r1), "=r"(r2), "=r"(r3) : "r"(addr));
}

__device__ __forceinline__ void mma16816(float* c, u32 a0, u32 a1, u32 a2, u32 a3,
                                         u32 b0, u32 b1) {
    asm volatile(
        "mma.sync.aligned.m16n8k16.row.col.f32.bf16.bf16.f32 "
        "{%0,%1,%2,%3}, {%4,%5,%6,%7}, {%8,%9}, {%0,%1,%2,%3};"
        : "+f"(c[0]), "+f"(c[1]), "+f"(c[2]), "+f"(c[3])
        : "r"(a0), "r"(a1), "r"(a2), "r"(a3), "r"(b0), "r"(b1));
}

__global__ __launch_bounds__(512) void gemm_mma_kernel(const float* __restrict__ X,
                                                       const unsigned short* __restrict__ Wh,
                                                       const unsigned short* __restrict__ Wl,
                                                       const float* __restrict__ dinv,
                                                       float* __restrict__ g, int n) {
    extern __shared__ char smem[];
    int tid = threadIdx.x;
    int wid = tid >> 5;
    int lane = tid & 31;
    int wr = wid >> 2;          // warp row group 0..3 (32 rows each)
    int wc = wid & 3;           // warp col group 0..3 (32 cols each)
    int row0 = blockIdx.x * 128;

    // ---- stage W hi/lo into smem (re-stride 128 -> SA) ----
    {
        const uint4* sh = (const uint4*)Wh;
        const uint4* sl = (const uint4*)Wl;
        for (int i = tid; i < 128 * 16; i += 512) {
            int r = i >> 4, c = i & 15;
            uint4 vh = sh[r * 16 + c];
            uint4 vl = sl[r * 16 + c];
            *(uint4*)(smem + SM_WH + (r * SA + c * 8) * 2) = vh;
            *(uint4*)(smem + SM_WL + (r * SA + c * 8) * 2) = vl;
        }
    }
    // ---- load X tile, split to bf16 hi/lo; thread: row=tid>>2, 32-col quarter ----
    {
        int r = tid >> 2;
        int quad = tid & 3;
        int row = row0 + r;
#pragma unroll
        for (int j = 0; j < 8; j++) {
            float4 v = (row < n)
                ? __ldg((const float4*)(X + (size_t)row * D + quad * 32) + j)
                : make_float4(0.f, 0.f, 0.f, 0.f);
            float f[4] = {v.x, v.y, v.z, v.w};
            unsigned short hs[4], ls[4];
#pragma unroll
            for (int p = 0; p < 4; p++) {
                __nv_bfloat16 hb = __float2bfloat16(f[p]);
                __nv_bfloat16 lb = __float2bfloat16(f[p] - __bfloat162float(hb));
                hs[p] = __bfloat16_as_ushort(hb);
                ls[p] = __bfloat16_as_ushort(lb);
            }
            int col = quad * 32 + j * 4;
            uint2 hw = make_uint2((u32)hs[0] | ((u32)hs[1] << 16),
                                  (u32)hs[2] | ((u32)hs[3] << 16));
            uint2 lw = make_uint2((u32)ls[0] | ((u32)ls[1] << 16),
                                  (u32)ls[2] | ((u32)ls[3] << 16));
            *(uint2*)(smem + SM_AH + (r * SA + col) * 2) = hw;
            *(uint2*)(smem + SM_AL + (r * SA + col) * 2) = lw;
        }
    }
    __syncthreads();

    // ---- mma mainloop ----
    float acc[2][4][4];
#pragma unroll
    for (int a = 0; a < 2; a++)
#pragma unroll
        for (int b = 0; b < 4; b++)
#pragma unroll
            for (int c = 0; c < 4; c++) acc[a][b][c] = 0.f;

    u32 sbase = smem_u32(smem);
    int gq = lane >> 3;
    int gr = lane & 7;
    // A fragment lane offsets for mtile 0/1 (16 rows each)
    u32 a_off0 = (u32)(((wr * 32 + (gq & 1) * 8 + gr) * SA + (gq >> 1) * 8) * 2);
    u32 a_off1 = a_off0 + (u32)(16 * SA * 2);
    // B fragment lane offset for this warp's 32-col group
    u32 b_off = (u32)(((wc * 32 + (gq >> 1) * 8 + gr) * SA + (gq & 1) * 8) * 2);

#pragma unroll
    for (int pass = 0; pass < 3; pass++) {
        u32 abase = sbase + (pass == 2 ? SM_AL : SM_AH);
        u32 bbase = sbase + (pass == 1 ? SM_WL : SM_WH) + b_off;
#pragma unroll
        for (int kt = 0; kt < 8; kt++) {
            u32 a0, a1, a2, a3, a4, a5, a6, a7;
            ldsm4(a0, a1, a2, a3, abase + a_off0 + kt * 32);
            ldsm4(a4, a5, a6, a7, abase + a_off1 + kt * 32);
            u32 b0, b1, b2, b3, b4, b5, b6, b7;
            ldsm4(b0, b1, b2, b3, bbase + kt * 32);
            ldsm4(b4, b5, b6, b7, bbase + kt * 32 + 16 * SA * 2);
            mma16816(acc[0][0], a0, a1, a2, a3, b0, b1);
            mma16816(acc[0][1], a0, a1, a2, a3, b2, b3);
            mma16816(acc[0][2], a0, a1, a2, a3, b4, b5);
            mma16816(acc[0][3], a0, a1, a2, a3, b6, b7);
            mma16816(acc[1][0], a4, a5, a6, a7, b0, b1);
            mma16816(acc[1][1], a4, a5, a6, a7, b2, b3);
            mma16816(acc[1][2], a4, a5, a6, a7, b4, b7 == b7 ? b5 : b5);
            mma16816(acc[1][3], a4, a5, a6, a7, b6, b7);
        }
    }

    // ---- epilogue: scale by dinv[row], store ----
    {
        int q = lane >> 2, p = lane & 3;
#pragma unroll
        for (int mt = 0; mt < 2; mt++) {
            int m0 = row0 + wr * 32 + mt * 16 + q;
            int m1 = m0 + 8;
            float dv0 = (m0 < n) ? dinv[m0] : 0.f;
            float dv1 = (m1 < n) ? dinv[m1] : 0.f;
#pragma unroll
            for (int nt = 0; nt < 4; nt++) {
                int col = wc * 32 + nt * 8 + p * 2;
                if (m0 < n)
                    *(float2*)(g + (size_t)m0 * D + col) =
                        make_float2(acc[mt][nt][0] * dv0, acc[mt][nt][1] * dv0);
                if (m1 < n)
                    *(float2*)(g + (size_t)m1 * D + col) =
                        make_float2(acc[mt][nt][2] * dv1, acc[mt][nt][3] * dv1);
            }
        }
    }
}

// ---------------------------------------------------------------------------
// Pull aggregation, f32x2-packed accumulate. Warp per node, lane owns 16B.
__global__ void gather_kernel(const int* __restrict__ csr,
                              const int* __restrict__ off,
                              const int* __restrict__ bsum,
                              const ulonglong2* __restrict__ g,
                              const float* __restrict__ dinv,
                              const float* __restrict__ bias,
                              float4* __restrict__ out, int n, int do_relu) {
    int gt = blockIdx.x * blockDim.x + threadIdx.x;
    int node = gt >> 5;
    int lane = gt & 31;
    if (node >= n) return;

    int end = off[node] + bsum[node >> 8];
    int start = (node > 0) ? (off[node - 1] + bsum[(node - 1) >> 8]) : 0;

    ulonglong2 s = g[(size_t)node * 32 + lane];   // self-loop term
    u64 ax = s.x, ay = s.y;

    int e = start;
    for (; e + 4 <= end; e += 4) {
        int s0 = csr[e], s1 = csr[e + 1], s2 = csr[e + 2], s3 = csr[e + 3];
        ulonglong2 v0 = g[(size_t)s0 * 32 + lane];
        ulonglong2 v1 = g[(size_t)s1 * 32 + lane];
        ulonglong2 v2 = g[(size_t)s2 * 32 + lane];
        ulonglong2 v3 = g[(size_t)s3 * 32 + lane];
        u64 t0, t1;
        ADD2(t0, v0.x, v1.x); ADD2(t1, v2.x, v3.x);
        ADD2(ax, ax, t0);     ADD2(ax, ax, t1);
        ADD2(t0, v0.y, v1.y); ADD2(t1, v2.y, v3.y);
        ADD2(ay, ay, t0);     ADD2(ay, ay, t1);
    }
    for (; e < end; e++) {
        int s2 = csr[e];
        ulonglong2 v = g[(size_t)s2 * 32 + lane];
        ADD2(ax, ax, v.x);
        ADD2(ay, ay, v.y);
    }

    u32 x0, x1, y0, y1;
    asm("mov.b64 {%0,%1}, %2;" : "=r"(x0), "=r"(x1) : "l"(ax));
    asm("mov.b64 {%0,%1}, %2;" : "=r"(y0), "=r"(y1) : "l"(ay));

    float dv = dinv[node];
    float4 bb = ((const float4*)bias)[lane];
    float4 o;
    o.x = __uint_as_float(x0) * dv + bb.x;
    o.y = __uint_as_float(x1) * dv + bb.y;
    o.z = __uint_as_float(y0) * dv + bb.z;
    o.w = __uint_as_float(y1) * dv + bb.w;
    if (do_relu) {
        o.x = fmaxf(o.x, 0.f); o.y = fmaxf(o.y, 0.f);
        o.z = fmaxf(o.z, 0.f); o.w = fmaxf(o.w, 0.f);
    }
    out[(size_t)node * 32 + lane] = o;
}

// ---------------------------------------------------------------------------
extern "C" void kernel_launch(void* const* d_in, const int* in_sizes, int n_in,
                              void* d_out, int out_size) {
    const float* x  = (const float*)d_in[0];
    const void*  ei = (const void*) d_in[1];
    const float* W1 = (const float*)d_in[2];
    const float* b1 = (const float*)d_in[3];
    const float* W2 = (const float*)d_in[4];
    const float* b2 = (const float*)d_in[5];
    float* out = (float*)d_out;

    int n = in_sizes[0] / D;
    int E = in_sizes[1] / 2;

    float *dinv, *gbuf, *h1;
    int *cnt, *off, *bsum, *csr;
    unsigned short *w1h, *w1l, *w2h, *w2l;
    cudaGetSymbolAddress((void**)&dinv, g_dinv);
    cudaGetSymbolAddress((void**)&gbuf, g_gbuf);
    cudaGetSymbolAddress((void**)&h1,   g_h1);
    cudaGetSymbolAddress((void**)&cnt,  g_cnt);
    cudaGetSymbolAddress((void**)&off,  g_off);
    cudaGetSymbolAddress((void**)&bsum, g_bsum);
    cudaGetSymbolAddress((void**)&csr,  g_csr);
    cudaGetSymbolAddress((void**)&w1h,  g_w1h);
    cudaGetSymbolAddress((void**)&w1l,  g_w1l);
    cudaGetSymbolAddress((void**)&w2h,  g_w2h);
    cudaGetSymbolAddress((void**)&w2l,  g_w2l);

    static int smem_set = 0;
    if (!smem_set) {
        cudaFuncSetAttribute(gemm_mma_kernel,
                             cudaFuncAttributeMaxDynamicSharedMemorySize, SM_TOTAL);
        smem_set = 1;
    }

    int prep_threads = (n > 2 * 128 * 128) ? n : 2 * 128 * 128;
    int nb_prep = (prep_threads + 255) / 256;
    int nb_edge = (E + 255) / 256;
    int nb_scan = (n + SCAN_BLK - 1) / SCAN_BLK;
    int gemm_blocks = (n + 127) / 128;
    long long gthreads = (long long)n * 32;
    int gather_blocks = (int)((gthreads + 255) / 256);

    // 0: prep (detect + zero cnt + weight split)
    prep_all_kernel<<<nb_prep, 256>>>(W1, W2, w1h, w1l, w2h, w2l,
                                      (const long long*)ei, E, cnt, n);
    // 1: histogram of dst
    hist_kernel<<<nb_edge, 256>>>(ei, cnt, E);
    // 2: block-local scan + dinv
    scan1_kernel<<<nb_scan, SCAN_BLK>>>(cnt, off, bsum, dinv, n);
    // 3: layer-1 GEMM (profiled slot)
    gemm_mma_kernel<<<gemm_blocks, 512, SM_TOTAL>>>(x, w1h, w1l, dinv, gbuf, n);
    // 4: scan of block sums
    scan2_kernel<<<1, SCAN_BLK>>>(bsum, nb_scan);
    // 5: CSR fill
    fill_kernel<<<nb_edge, 256>>>(ei, off, bsum, csr, E);
    // 6: layer-1 gather
    gather_kernel<<<gather_blocks, 256>>>(csr, off, bsum, (const ulonglong2*)gbuf,
                                          dinv, b1, (float4*)h1, n, 1);
    // 7: layer-2 GEMM
    gemm_mma_kernel<<<gemm_blocks, 512, SM_TOTAL>>>(h1, w2h, w2l, dinv, gbuf, n);
    // 8: layer-2 gather
    gather_kernel<<<gather_blocks, 256>>>(csr, off, bsum, (const ulonglong2*)gbuf,
                                          dinv, b2, (float4*)out, n, 0);
}

// round 8
// speedup vs baseline: 2.5471x; 1.0835x over previous
#include <cuda_runtime.h>
#include <cuda_bf16.h>
#include <cstdint>

using u32 = unsigned int;
using u64 = unsigned long long;

#define D 128
#define MAXN 50048
#define MAXE 800000
#define SCAN_BLK 256
#define NB_SCAN ((MAXN + SCAN_BLK - 1) / SCAN_BLK)

// ---------------------------------------------------------------------------
// Scratch (device globals: no allocation allowed)
__device__ float g_dinv[MAXN];
__device__ float g_gbuf[(size_t)MAXN * D];
__device__ float g_h1[(size_t)MAXN * D];
__device__ int   g_cnt[MAXN];
__device__ int   g_off[MAXN];
__device__ int   g_bsum[NB_SCAN];
__device__ int   g_csr[MAXE];
__device__ int   g_is32;
// Pre-transposed, bf16-split weights: Wt[n][k] = W[k][n], row-major [128][128]
__device__ unsigned short g_w1h[128 * 128];
__device__ unsigned short g_w1l[128 * 128];
__device__ unsigned short g_w2h[128 * 128];
__device__ unsigned short g_w2l[128 * 128];

__device__ __forceinline__ int load_idx(const void* ei, size_t pos) {
    if (g_is32) return ((const int*)ei)[pos];
    return (int)((const long long*)ei)[pos];
}

// packed fp32x2 add (sm_100+ baseline PTX)
#define ADD2(o, a, b) asm("add.rn.f32x2 %0, %1, %2;" : "=l"(o) : "l"(a), "l"(b))

// ---------------------------------------------------------------------------
// Fused: edge-dtype detect + cnt zero + weight transpose/bf16-split.
__global__ void prep_all_kernel(const float* __restrict__ W1,
                                const float* __restrict__ W2,
                                unsigned short* w1h, unsigned short* w1l,
                                unsigned short* w2h, unsigned short* w2l,
                                const long long* __restrict__ ei, int E,
                                int* cnt, int n) {
    int i = blockIdx.x * blockDim.x + threadIdx.x;
    if (i == 0) {
        int is32 = 0;
        int m = E < 64 ? E : 64;
        for (int t = 0; t < m; t++) {
            long long v = ei[t];
            if (v < 0 || v >= (long long)n) { is32 = 1; break; }
        }
        g_is32 = is32;
    }
    if (i < n) cnt[i] = 0;
    if (i < 2 * 128 * 128) {
        int which = i >> 14;
        int j = i & 16383;
        int k = j >> 7, nn = j & 127;
        const float* W = which ? W2 : W1;
        float v = W[k * 128 + nn];
        __nv_bfloat16 hb = __float2bfloat16(v);
        __nv_bfloat16 lb = __float2bfloat16(v - __bfloat162float(hb));
        int off = nn * 128 + k;
        (which ? w2h : w1h)[off] = __bfloat16_as_ushort(hb);
        (which ? w2l : w1l)[off] = __bfloat16_as_ushort(lb);
    }
}

// ---------------------------------------------------------------------------
__global__ void hist_kernel(const void* __restrict__ ei, int* cnt, int E) {
    int e = blockIdx.x * blockDim.x + threadIdx.x;
    if (e < E) atomicAdd(&cnt[load_idx(ei, (size_t)E + e)], 1);
}

// Block-local exclusive scan over cnt -> off; per-block sums -> bsum; also dinv.
__global__ void scan1_kernel(const int* __restrict__ cnt, int* off, int* bsum,
                             float* dinv, int n) {
    __shared__ int s[SCAN_BLK];
    int i = blockIdx.x * SCAN_BLK + threadIdx.x;
    int v = (i < n) ? cnt[i] : 0;
    if (i < n) dinv[i] = rsqrtf((float)v + 1.0f);   // +1 self-loop
    s[threadIdx.x] = v;
    __syncthreads();
#pragma unroll
    for (int d = 1; d < SCAN_BLK; d <<= 1) {
        int t = (threadIdx.x >= d) ? s[threadIdx.x - d] : 0;
        __syncthreads();
        s[threadIdx.x] += t;
        __syncthreads();
    }
    if (i < n) off[i] = s[threadIdx.x] - v;        // block-local exclusive
    if (threadIdx.x == SCAN_BLK - 1) bsum[blockIdx.x] = s[SCAN_BLK - 1];
}

__global__ void scan2_kernel(int* bsum, int nb) {
    __shared__ int s[SCAN_BLK];
    int v = (threadIdx.x < nb) ? bsum[threadIdx.x] : 0;
    s[threadIdx.x] = v;
    __syncthreads();
#pragma unroll
    for (int d = 1; d < SCAN_BLK; d <<= 1) {
        int t = (threadIdx.x >= d) ? s[threadIdx.x - d] : 0;
        __syncthreads();
        s[threadIdx.x] += t;
        __syncthreads();
    }
    if (threadIdx.x < nb) bsum[threadIdx.x] = s[threadIdx.x] - v;  // exclusive
}

// fill CSR: global pos = local cursor + bsum[block of d]
__global__ void fill_kernel(const void* __restrict__ ei, int* off,
                            const int* __restrict__ bsum, int* csr, int E) {
    int e = blockIdx.x * blockDim.x + threadIdx.x;
    if (e < E) {
        int s = load_idx(ei, (size_t)e);
        int d = load_idx(ei, (size_t)E + e);
        int pos = atomicAdd(&off[d], 1) + bsum[d >> 8];
        csr[pos] = s;
    }
}

// ---------------------------------------------------------------------------
// bf16-split GEMM via mma.sync (HMMA): g[row] = (X[row] @ W) * dinv[row]
// acc(fp32) = Ah@Bh + Ah@Bl + Al@Bh  (residual ~2^-16)
// CTA: 512 thr / 16 warps in 4x4 grid; warp owns 32 rows x 32 cols.
// Fused k-loop: per kt load Ah/Al/Bh/Bl frags once (8 ldsm4), issue all 24 MMAs.
#define SA 136
#define SM_AH 0
#define SM_AL (128 * SA * 2)
#define SM_WH (2 * 128 * SA * 2)
#define SM_WL (3 * 128 * SA * 2)
#define SM_TOTAL (4 * 128 * SA * 2)

__device__ __forceinline__ u32 smem_u32(const void* p) {
    u32 a;
    asm("{ .reg .u64 t; cvta.to.shared.u64 t, %1; cvt.u32.u64 %0, t; }" : "=r"(a) : "l"(p));
    return a;
}

__device__ __forceinline__ void ldsm4(u32* r, u32 addr) {
    asm volatile("ldmatrix.sync.aligned.m8n8.x4.shared.b16 {%0,%1,%2,%3}, [%4];"
                 : "=r"(r[0]), "=r"(r[1]), "=r"(r[2]), "=r"(r[3]) : "r"(addr));
}

__device__ __forceinline__ void mma16816(float* c, const u32* a, u32 b0, u32 b1) {
    asm volatile(
        "mma.sync.aligned.m16n8k16.row.col.f32.bf16.bf16.f32 "
        "{%0,%1,%2,%3}, {%4,%5,%6,%7}, {%8,%9}, {%0,%1,%2,%3};"
        : "+f"(c[0]), "+f"(c[1]), "+f"(c[2]), "+f"(c[3])
        : "r"(a[0]), "r"(a[1]), "r"(a[2]), "r"(a[3]), "r"(b0), "r"(b1));
}

__global__ __launch_bounds__(512) void gemm_mma_kernel(const float* __restrict__ X,
                                                       const unsigned short* __restrict__ Wh,
                                                       const unsigned short* __restrict__ Wl,
                                                       const float* __restrict__ dinv,
                                                       float* __restrict__ g, int n) {
    extern __shared__ char smem[];
    int tid = threadIdx.x;
    int wid = tid >> 5;
    int lane = tid & 31;
    int wr = wid >> 2;          // warp row group 0..3 (32 rows each)
    int wc = wid & 3;           // warp col group 0..3 (32 cols each)
    int row0 = blockIdx.x * 128;

    // ---- stage W hi/lo into smem (re-stride 128 -> SA) ----
    {
        const uint4* sh = (const uint4*)Wh;
        const uint4* sl = (const uint4*)Wl;
        for (int i = tid; i < 128 * 16; i += 512) {
            int r = i >> 4, c = i & 15;
            uint4 vh = sh[r * 16 + c];
            uint4 vl = sl[r * 16 + c];
            *(uint4*)(smem + SM_WH + (r * SA + c * 8) * 2) = vh;
            *(uint4*)(smem + SM_WL + (r * SA + c * 8) * 2) = vl;
        }
    }
    // ---- load X tile, split to bf16 hi/lo; thread: row=tid>>2, 32-col quarter ----
    {
        int r = tid >> 2;
        int quad = tid & 3;
        int row = row0 + r;
#pragma unroll
        for (int j = 0; j < 8; j++) {
            float4 v = (row < n)
                ? __ldg((const float4*)(X + (size_t)row * D + quad * 32) + j)
                : make_float4(0.f, 0.f, 0.f, 0.f);
            float f[4] = {v.x, v.y, v.z, v.w};
            unsigned short hs[4], ls[4];
#pragma unroll
            for (int p = 0; p < 4; p++) {
                __nv_bfloat16 hb = __float2bfloat16(f[p]);
                __nv_bfloat16 lb = __float2bfloat16(f[p] - __bfloat162float(hb));
                hs[p] = __bfloat16_as_ushort(hb);
                ls[p] = __bfloat16_as_ushort(lb);
            }
            int col = quad * 32 + j * 4;
            uint2 hw = make_uint2((u32)hs[0] | ((u32)hs[1] << 16),
                                  (u32)hs[2] | ((u32)hs[3] << 16));
            uint2 lw = make_uint2((u32)ls[0] | ((u32)ls[1] << 16),
                                  (u32)ls[2] | ((u32)ls[3] << 16));
            *(uint2*)(smem + SM_AH + (r * SA + col) * 2) = hw;
            *(uint2*)(smem + SM_AL + (r * SA + col) * 2) = lw;
        }
    }
    __syncthreads();

    // ---- fused mma mainloop ----
    float acc[2][4][4];
#pragma unroll
    for (int a = 0; a < 2; a++)
#pragma unroll
        for (int b = 0; b < 4; b++)
#pragma unroll
            for (int c = 0; c < 4; c++) acc[a][b][c] = 0.f;

    u32 sbase = smem_u32(smem);
    int gq = lane >> 3;
    int gr = lane & 7;
    // A fragment lane offsets (within a tile) for mtile 0/1 (16 rows each)
    u32 a_off0 = (u32)(((wr * 32 + (gq & 1) * 8 + gr) * SA + (gq >> 1) * 8) * 2);
    u32 a_off1 = a_off0 + (u32)(16 * SA * 2);
    // B fragment lane offset for this warp's 32-col group
    u32 b_off = (u32)(((wc * 32 + (gq >> 1) * 8 + gr) * SA + (gq & 1) * 8) * 2);

#pragma unroll
    for (int kt = 0; kt < 8; kt++) {
        u32 ah[8], al[8], bh[8], bl[8];
        ldsm4(ah,     sbase + SM_AH + a_off0 + kt * 32);
        ldsm4(ah + 4, sbase + SM_AH + a_off1 + kt * 32);
        ldsm4(al,     sbase + SM_AL + a_off0 + kt * 32);
        ldsm4(al + 4, sbase + SM_AL + a_off1 + kt * 32);
        ldsm4(bh,     sbase + SM_WH + b_off + kt * 32);
        ldsm4(bh + 4, sbase + SM_WH + b_off + 16 * SA * 2 + kt * 32);
        ldsm4(bl,     sbase + SM_WL + b_off + kt * 32);
        ldsm4(bl + 4, sbase + SM_WL + b_off + 16 * SA * 2 + kt * 32);

        // pass Ah*Bh (8 independent MMAs)
#pragma unroll
        for (int nt = 0; nt < 4; nt++) {
            mma16816(acc[0][nt], ah,     bh[2 * nt], bh[2 * nt + 1]);
            mma16816(acc[1][nt], ah + 4, bh[2 * nt], bh[2 * nt + 1]);
        }
        // pass Ah*Bl
#pragma unroll
        for (int nt = 0; nt < 4; nt++) {
            mma16816(acc[0][nt], ah,     bl[2 * nt], bl[2 * nt + 1]);
            mma16816(acc[1][nt], ah + 4, bl[2 * nt], bl[2 * nt + 1]);
        }
        // pass Al*Bh
#pragma unroll
        for (int nt = 0; nt < 4; nt++) {
            mma16816(acc[0][nt], al,     bh[2 * nt], bh[2 * nt + 1]);
            mma16816(acc[1][nt], al + 4, bh[2 * nt], bh[2 * nt + 1]);
        }
    }

    // ---- epilogue: scale by dinv[row], store ----
    {
        int q = lane >> 2, p = lane & 3;
#pragma unroll
        for (int mt = 0; mt < 2; mt++) {
            int m0 = row0 + wr * 32 + mt * 16 + q;
            int m1 = m0 + 8;
            float dv0 = (m0 < n) ? dinv[m0] : 0.f;
            float dv1 = (m1 < n) ? dinv[m1] : 0.f;
#pragma unroll
            for (int nt = 0; nt < 4; nt++) {
                int col = wc * 32 + nt * 8 + p * 2;
                if (m0 < n)
                    *(float2*)(g + (size_t)m0 * D + col) =
                        make_float2(acc[mt][nt][0] * dv0, acc[mt][nt][1] * dv0);
                if (m1 < n)
                    *(float2*)(g + (size_t)m1 * D + col) =
                        make_float2(acc[mt][nt][2] * dv1, acc[mt][nt][3] * dv1);
            }
        }
    }
}

// ---------------------------------------------------------------------------
// Pull aggregation, f32x2-packed accumulate. Warp per node, lane owns 16B.
__global__ void gather_kernel(const int* __restrict__ csr,
                              const int* __restrict__ off,
                              const int* __restrict__ bsum,
                              const ulonglong2* __restrict__ g,
                              const float* __restrict__ dinv,
                              const float* __restrict__ bias,
                              float4* __restrict__ out, int n, int do_relu) {
    int gt = blockIdx.x * blockDim.x + threadIdx.x;
    int node = gt >> 5;
    int lane = gt & 31;
    if (node >= n) return;

    int end = off[node] + bsum[node >> 8];
    int start = (node > 0) ? (off[node - 1] + bsum[(node - 1) >> 8]) : 0;

    ulonglong2 s = g[(size_t)node * 32 + lane];   // self-loop term
    u64 ax = s.x, ay = s.y;

    int e = start;
    for (; e + 4 <= end; e += 4) {
        int s0 = csr[e], s1 = csr[e + 1], s2 = csr[e + 2], s3 = csr[e + 3];
        ulonglong2 v0 = g[(size_t)s0 * 32 + lane];
        ulonglong2 v1 = g[(size_t)s1 * 32 + lane];
        ulonglong2 v2 = g[(size_t)s2 * 32 + lane];
        ulonglong2 v3 = g[(size_t)s3 * 32 + lane];
        u64 t0, t1;
        ADD2(t0, v0.x, v1.x); ADD2(t1, v2.x, v3.x);
        ADD2(ax, ax, t0);     ADD2(ax, ax, t1);
        ADD2(t0, v0.y, v1.y); ADD2(t1, v2.y, v3.y);
        ADD2(ay, ay, t0);     ADD2(ay, ay, t1);
    }
    for (; e < end; e++) {
        int s2 = csr[e];
        ulonglong2 v = g[(size_t)s2 * 32 + lane];
        ADD2(ax, ax, v.x);
        ADD2(ay, ay, v.y);
    }

    u32 x0, x1, y0, y1;
    asm("mov.b64 {%0,%1}, %2;" : "=r"(x0), "=r"(x1) : "l"(ax));
    asm("mov.b64 {%0,%1}, %2;" : "=r"(y0), "=r"(y1) : "l"(ay));

    float dv = dinv[node];
    float4 bb = ((const float4*)bias)[lane];
    float4 o;
    o.x = __uint_as_float(x0) * dv + bb.x;
    o.y = __uint_as_float(x1) * dv + bb.y;
    o.z = __uint_as_float(y0) * dv + bb.z;
    o.w = __uint_as_float(y1) * dv + bb.w;
    if (do_relu) {
        o.x = fmaxf(o.x, 0.f); o.y = fmaxf(o.y, 0.f);
        o.z = fmaxf(o.z, 0.f); o.w = fmaxf(o.w, 0.f);
    }
    out[(size_t)node * 32 + lane] = o;
}

// ---------------------------------------------------------------------------
extern "C" void kernel_launch(void* const* d_in, const int* in_sizes, int n_in,
                              void* d_out, int out_size) {
    const float* x  = (const float*)d_in[0];
    const void*  ei = (const void*) d_in[1];
    const float* W1 = (const float*)d_in[2];
    const float* b1 = (const float*)d_in[3];
    const float* W2 = (const float*)d_in[4];
    const float* b2 = (const float*)d_in[5];
    float* out = (float*)d_out;

    int n = in_sizes[0] / D;
    int E = in_sizes[1] / 2;

    float *dinv, *gbuf, *h1;
    int *cnt, *off, *bsum, *csr;
    unsigned short *w1h, *w1l, *w2h, *w2l;
    cudaGetSymbolAddress((void**)&dinv, g_dinv);
    cudaGetSymbolAddress((void**)&gbuf, g_gbuf);
    cudaGetSymbolAddress((void**)&h1,   g_h1);
    cudaGetSymbolAddress((void**)&cnt,  g_cnt);
    cudaGetSymbolAddress((void**)&off,  g_off);
    cudaGetSymbolAddress((void**)&bsum, g_bsum);
    cudaGetSymbolAddress((void**)&csr,  g_csr);
    cudaGetSymbolAddress((void**)&w1h,  g_w1h);
    cudaGetSymbolAddress((void**)&w1l,  g_w1l);
    cudaGetSymbolAddress((void**)&w2h,  g_w2h);
    cudaGetSymbolAddress((void**)&w2l,  g_w2l);

    static int smem_set = 0;
    if (!smem_set) {
        cudaFuncSetAttribute(gemm_mma_kernel,
                             cudaFuncAttributeMaxDynamicSharedMemorySize, SM_TOTAL);
        smem_set = 1;
    }

    int prep_threads = (n > 2 * 128 * 128) ? n : 2 * 128 * 128;
    int nb_prep = (prep_threads + 255) / 256;
    int nb_edge = (E + 255) / 256;
    int nb_scan = (n + SCAN_BLK - 1) / SCAN_BLK;
    int gemm_blocks = (n + 127) / 128;
    long long gthreads = (long long)n * 32;
    int gather_blocks = (int)((gthreads + 255) / 256);

    // 0: prep (detect + zero cnt + weight split)
    prep_all_kernel<<<nb_prep, 256>>>(W1, W2, w1h, w1l, w2h, w2l,
                                      (const long long*)ei, E, cnt, n);
    // 1: histogram of dst
    hist_kernel<<<nb_edge, 256>>>(ei, cnt, E);
    // 2: block-local scan + dinv
    scan1_kernel<<<nb_scan, SCAN_BLK>>>(cnt, off, bsum, dinv, n);
    // 3: layer-1 GEMM (profiled slot)
    gemm_mma_kernel<<<gemm_blocks, 512, SM_TOTAL>>>(x, w1h, w1l, dinv, gbuf, n);
    // 4: scan of block sums
    scan2_kernel<<<1, SCAN_BLK>>>(bsum, nb_scan);
    // 5: CSR fill
    fill_kernel<<<nb_edge, 256>>>(ei, off, bsum, csr, E);
    // 6: layer-1 gather
    gather_kernel<<<gather_blocks, 256>>>(csr, off, bsum, (const ulonglong2*)gbuf,
                                          dinv, b1, (float4*)h1, n, 1);
    // 7: layer-2 GEMM
    gemm_mma_kernel<<<gemm_blocks, 512, SM_TOTAL>>>(h1, w2h, w2l, dinv, gbuf, n);
    // 8: layer-2 gather
    gather_kernel<<<gather_blocks, 256>>>(csr, off, bsum, (const ulonglong2*)gbuf,
                                          dinv, b2, (float4*)out, n, 0);
}

// round 9
// speedup vs baseline: 2.6270x; 1.0314x over previous
#include <cuda_runtime.h>
#include <cuda_bf16.h>
#include <cstdint>

using u32 = unsigned int;
using u64 = unsigned long long;

#define D 128
#define MAXN 50048
#define MAXE 800000
#define SCAN_BLK 256
#define NB_SCAN ((MAXN + SCAN_BLK - 1) / SCAN_BLK)
#define SA 136   // smem row stride in bf16 elems (272B, ldsm conflict-free)

// ---------------------------------------------------------------------------
// Scratch (device globals: no allocation allowed)
__device__ float g_dinv[MAXN];
__device__ float g_gbuf[(size_t)MAXN * D];
__device__ float g_h1[(size_t)MAXN * D];
__device__ int   g_cnt[MAXN];
__device__ int   g_off[MAXN];
__device__ int   g_bsum[NB_SCAN];
__device__ int   g_csr[MAXE];
__device__ int   g_is32;
// Pre-transposed, bf16-split weights in SA-strided layout: [n][k] at n*SA+k
__device__ unsigned short g_w1h[128 * SA];
__device__ unsigned short g_w1l[128 * SA];
__device__ unsigned short g_w2h[128 * SA];
__device__ unsigned short g_w2l[128 * SA];

__device__ __forceinline__ int load_idx(const void* ei, size_t pos) {
    if (g_is32) return ((const int*)ei)[pos];
    return (int)((const long long*)ei)[pos];
}

// packed fp32x2 add (sm_100+ baseline PTX)
#define ADD2(o, a, b) asm("add.rn.f32x2 %0, %1, %2;" : "=l"(o) : "l"(a), "l"(b))

__device__ __forceinline__ void cp_async16(u32 saddr, const void* gaddr) {
    asm volatile("cp.async.ca.shared.global [%0], [%1], 16;"
                 :: "r"(saddr), "l"(gaddr));
}

// ---------------------------------------------------------------------------
// Fused: edge-dtype detect + cnt zero + weight transpose/bf16-split (SA layout).
__global__ void prep_all_kernel(const float* __restrict__ W1,
                                const float* __restrict__ W2,
                                unsigned short* w1h, unsigned short* w1l,
                                unsigned short* w2h, unsigned short* w2l,
                                const long long* __restrict__ ei, int E,
                                int* cnt, int n) {
    int i = blockIdx.x * blockDim.x + threadIdx.x;
    if (i == 0) {
        int is32 = 0;
        int m = E < 64 ? E : 64;
        for (int t = 0; t < m; t++) {
            long long v = ei[t];
            if (v < 0 || v >= (long long)n) { is32 = 1; break; }
        }
        g_is32 = is32;
    }
    if (i < n) cnt[i] = 0;
    if (i < 2 * 128 * 128) {
        int which = i >> 14;
        int j = i & 16383;
        int k = j >> 7, nn = j & 127;
        const float* W = which ? W2 : W1;
        float v = W[k * 128 + nn];
        __nv_bfloat16 hb = __float2bfloat16(v);
        __nv_bfloat16 lb = __float2bfloat16(v - __bfloat162float(hb));
        int off = nn * SA + k;
        (which ? w2h : w1h)[off] = __bfloat16_as_ushort(hb);
        (which ? w2l : w1l)[off] = __bfloat16_as_ushort(lb);
    }
}

// ---------------------------------------------------------------------------
__global__ void hist_kernel(const void* __restrict__ ei, int* cnt, int E) {
    int e = blockIdx.x * blockDim.x + threadIdx.x;
    if (e < E) atomicAdd(&cnt[load_idx(ei, (size_t)E + e)], 1);
}

// Block-local exclusive scan over cnt -> off; per-block sums -> bsum; also dinv.
__global__ void scan1_kernel(const int* __restrict__ cnt, int* off, int* bsum,
                             float* dinv, int n) {
    __shared__ int s[SCAN_BLK];
    int i = blockIdx.x * SCAN_BLK + threadIdx.x;
    int v = (i < n) ? cnt[i] : 0;
    if (i < n) dinv[i] = rsqrtf((float)v + 1.0f);   // +1 self-loop
    s[threadIdx.x] = v;
    __syncthreads();
#pragma unroll
    for (int d = 1; d < SCAN_BLK; d <<= 1) {
        int t = (threadIdx.x >= d) ? s[threadIdx.x - d] : 0;
        __syncthreads();
        s[threadIdx.x] += t;
        __syncthreads();
    }
    if (i < n) off[i] = s[threadIdx.x] - v;        // block-local exclusive
    if (threadIdx.x == SCAN_BLK - 1) bsum[blockIdx.x] = s[SCAN_BLK - 1];
}

__global__ void scan2_kernel(int* bsum, int nb) {
    __shared__ int s[SCAN_BLK];
    int v = (threadIdx.x < nb) ? bsum[threadIdx.x] : 0;
    s[threadIdx.x] = v;
    __syncthreads();
#pragma unroll
    for (int d = 1; d < SCAN_BLK; d <<= 1) {
        int t = (threadIdx.x >= d) ? s[threadIdx.x - d] : 0;
        __syncthreads();
        s[threadIdx.x] += t;
        __syncthreads();
    }
    if (threadIdx.x < nb) bsum[threadIdx.x] = s[threadIdx.x] - v;  // exclusive
}

// fill CSR: global pos = local cursor + bsum[block of d]
__global__ void fill_kernel(const void* __restrict__ ei, int* off,
                            const int* __restrict__ bsum, int* csr, int E) {
    int e = blockIdx.x * blockDim.x + threadIdx.x;
    if (e < E) {
        int s = load_idx(ei, (size_t)e);
        int d = load_idx(ei, (size_t)E + e);
        int pos = atomicAdd(&off[d], 1) + bsum[d >> 8];
        csr[pos] = s;
    }
}

// ---------------------------------------------------------------------------
// bf16-split GEMM via mma.sync (HMMA): g[row] = (X[row] @ W) * dinv[row]
// acc(fp32) = Ah@Bh + Ah@Bl + Al@Bh  (residual ~2^-16)
// CTA: 256 thr / 8 warps in 2x4 grid; warp owns 32 rows x 32 cols.
// Tile 64 rows -> smem 104.4KB -> 2 CTAs/SM (prologue/mainloop overlap).
#define SM_AH 0
#define SM_AL (64 * SA * 2)
#define SM_WH (2 * 64 * SA * 2)
#define SM_WL (SM_WH + 128 * SA * 2)
#define SM_TOTAL (SM_WL + 128 * SA * 2)

__device__ __forceinline__ u32 smem_u32(const void* p) {
    u32 a;
    asm("{ .reg .u64 t; cvta.to.shared.u64 t, %1; cvt.u32.u64 %0, t; }" : "=r"(a) : "l"(p));
    return a;
}

__device__ __forceinline__ void ldsm4(u32* r, u32 addr) {
    asm volatile("ldmatrix.sync.aligned.m8n8.x4.shared.b16 {%0,%1,%2,%3}, [%4];"
                 : "=r"(r[0]), "=r"(r[1]), "=r"(r[2]), "=r"(r[3]) : "r"(addr));
}

__device__ __forceinline__ void mma16816(float* c, const u32* a, u32 b0, u32 b1) {
    asm volatile(
        "mma.sync.aligned.m16n8k16.row.col.f32.bf16.bf16.f32 "
        "{%0,%1,%2,%3}, {%4,%5,%6,%7}, {%8,%9}, {%0,%1,%2,%3};"
        : "+f"(c[0]), "+f"(c[1]), "+f"(c[2]), "+f"(c[3])
        : "r"(a[0]), "r"(a[1]), "r"(a[2]), "r"(a[3]), "r"(b0), "r"(b1));
}

__global__ __launch_bounds__(256) void gemm_mma_kernel(const float* __restrict__ X,
                                                       const unsigned short* __restrict__ Wh,
                                                       const unsigned short* __restrict__ Wl,
                                                       const float* __restrict__ dinv,
                                                       float* __restrict__ g, int n) {
    extern __shared__ char smem[];
    u32 sbase = smem_u32(smem);
    int tid = threadIdx.x;
    int wid = tid >> 5;
    int lane = tid & 31;
    int wr = wid >> 2;          // warp row group 0..1 (32 rows each)
    int wc = wid & 3;           // warp col group 0..3 (32 cols each)
    int row0 = blockIdx.x * 64;

    // ---- stage W hi/lo via cp.async (already SA-strided in global) ----
    {
        // 128*SA shorts = 34816B per tile = 2176 x 16B; two tiles = 4352 chunks
        const char* gh = (const char*)Wh;
        const char* gl = (const char*)Wl;
        for (int i = tid; i < 2176; i += 256) {
            cp_async16(sbase + SM_WH + i * 16, gh + i * 16);
            cp_async16(sbase + SM_WL + i * 16, gl + i * 16);
        }
        asm volatile("cp.async.commit_group;");
    }
    // ---- load X tile (64 rows), split to bf16 hi/lo ----
    {
        int r = tid >> 2;           // 0..63
        int quad = tid & 3;
        int row = row0 + r;
#pragma unroll
        for (int j = 0; j < 8; j++) {
            float4 v = (row < n)
                ? __ldg((const float4*)(X + (size_t)row * D + quad * 32) + j)
                : make_float4(0.f, 0.f, 0.f, 0.f);
            float f[4] = {v.x, v.y, v.z, v.w};
            unsigned short hs[4], ls[4];
#pragma unroll
            for (int p = 0; p < 4; p++) {
                __nv_bfloat16 hb = __float2bfloat16(f[p]);
                __nv_bfloat16 lb = __float2bfloat16(f[p] - __bfloat162float(hb));
                hs[p] = __bfloat16_as_ushort(hb);
                ls[p] = __bfloat16_as_ushort(lb);
            }
            int col = quad * 32 + j * 4;
            uint2 hw = make_uint2((u32)hs[0] | ((u32)hs[1] << 16),
                                  (u32)hs[2] | ((u32)hs[3] << 16));
            uint2 lw = make_uint2((u32)ls[0] | ((u32)ls[1] << 16),
                                  (u32)ls[2] | ((u32)ls[3] << 16));
            *(uint2*)(smem + SM_AH + (r * SA + col) * 2) = hw;
            *(uint2*)(smem + SM_AL + (r * SA + col) * 2) = lw;
        }
    }
    asm volatile("cp.async.wait_group 0;" ::: "memory");
    __syncthreads();

    // ---- fused mma mainloop ----
    float acc[2][4][4];
#pragma unroll
    for (int a = 0; a < 2; a++)
#pragma unroll
        for (int b = 0; b < 4; b++)
#pragma unroll
            for (int c = 0; c < 4; c++) acc[a][b][c] = 0.f;

    int gq = lane >> 3;
    int gr = lane & 7;
    // A fragment lane offsets for the warp's 32 rows (two 16-row mtiles)
    u32 a_off0 = (u32)(((wr * 32 + (gq & 1) * 8 + gr) * SA + (gq >> 1) * 8) * 2);
    u32 a_off1 = a_off0 + (u32)(16 * SA * 2);
    // B fragment lane offset for this warp's 32-col group
    u32 b_off = (u32)(((wc * 32 + (gq >> 1) * 8 + gr) * SA + (gq & 1) * 8) * 2);

#pragma unroll
    for (int kt = 0; kt < 8; kt++) {
        u32 ah[8], al[8], bh[8], bl[8];
        ldsm4(ah,     sbase + SM_AH + a_off0 + kt * 32);
        ldsm4(ah + 4, sbase + SM_AH + a_off1 + kt * 32);
        ldsm4(al,     sbase + SM_AL + a_off0 + kt * 32);
        ldsm4(al + 4, sbase + SM_AL + a_off1 + kt * 32);
        ldsm4(bh,     sbase + SM_WH + b_off + kt * 32);
        ldsm4(bh + 4, sbase + SM_WH + b_off + 16 * SA * 2 + kt * 32);
        ldsm4(bl,     sbase + SM_WL + b_off + kt * 32);
        ldsm4(bl + 4, sbase + SM_WL + b_off + 16 * SA * 2 + kt * 32);

#pragma unroll
        for (int nt = 0; nt < 4; nt++) {
            mma16816(acc[0][nt], ah,     bh[2 * nt], bh[2 * nt + 1]);
            mma16816(acc[1][nt], ah + 4, bh[2 * nt], bh[2 * nt + 1]);
        }
#pragma unroll
        for (int nt = 0; nt < 4; nt++) {
            mma16816(acc[0][nt], ah,     bl[2 * nt], bl[2 * nt + 1]);
            mma16816(acc[1][nt], ah + 4, bl[2 * nt], bl[2 * nt + 1]);
        }
#pragma unroll
        for (int nt = 0; nt < 4; nt++) {
            mma16816(acc[0][nt], al,     bh[2 * nt], bh[2 * nt + 1]);
            mma16816(acc[1][nt], al + 4, bh[2 * nt], bh[2 * nt + 1]);
        }
    }

    // ---- epilogue: scale by dinv[row], store ----
    {
        int q = lane >> 2, p = lane & 3;
#pragma unroll
        for (int mt = 0; mt < 2; mt++) {
            int m0 = row0 + wr * 32 + mt * 16 + q;
            int m1 = m0 + 8;
            float dv0 = (m0 < n) ? dinv[m0] : 0.f;
            float dv1 = (m1 < n) ? dinv[m1] : 0.f;
#pragma unroll
            for (int nt = 0; nt < 4; nt++) {
                int col = wc * 32 + nt * 8 + p * 2;
                if (m0 < n)
                    *(float2*)(g + (size_t)m0 * D + col) =
                        make_float2(acc[mt][nt][0] * dv0, acc[mt][nt][1] * dv0);
                if (m1 < n)
                    *(float2*)(g + (size_t)m1 * D + col) =
                        make_float2(acc[mt][nt][2] * dv1, acc[mt][nt][3] * dv1);
            }
        }
    }
}

// ---------------------------------------------------------------------------
// Pull aggregation, f32x2-packed accumulate. Warp per node, lane owns 16B.
__global__ void gather_kernel(const int* __restrict__ csr,
                              const int* __restrict__ off,
                              const int* __restrict__ bsum,
                              const ulonglong2* __restrict__ g,
                              const float* __restrict__ dinv,
                              const float* __restrict__ bias,
                              float4* __restrict__ out, int n, int do_relu) {
    int gt = blockIdx.x * blockDim.x + threadIdx.x;
    int node = gt >> 5;
    int lane = gt & 31;
    if (node >= n) return;

    int end = off[node] + bsum[node >> 8];
    int start = (node > 0) ? (off[node - 1] + bsum[(node - 1) >> 8]) : 0;

    ulonglong2 s = g[(size_t)node * 32 + lane];   // self-loop term
    u64 ax = s.x, ay = s.y;

    int e = start;
    for (; e + 4 <= end; e += 4) {
        int s0 = csr[e], s1 = csr[e + 1], s2 = csr[e + 2], s3 = csr[e + 3];
        ulonglong2 v0 = g[(size_t)s0 * 32 + lane];
        ulonglong2 v1 = g[(size_t)s1 * 32 + lane];
        ulonglong2 v2 = g[(size_t)s2 * 32 + lane];
        ulonglong2 v3 = g[(size_t)s3 * 32 + lane];
        u64 t0, t1;
        ADD2(t0, v0.x, v1.x); ADD2(t1, v2.x, v3.x);
        ADD2(ax, ax, t0);     ADD2(ax, ax, t1);
        ADD2(t0, v0.y, v1.y); ADD2(t1, v2.y, v3.y);
        ADD2(ay, ay, t0);     ADD2(ay, ay, t1);
    }
    for (; e < end; e++) {
        int s2 = csr[e];
        ulonglong2 v = g[(size_t)s2 * 32 + lane];
        ADD2(ax, ax, v.x);
        ADD2(ay, ay, v.y);
    }

    u32 x0, x1, y0, y1;
    asm("mov.b64 {%0,%1}, %2;" : "=r"(x0), "=r"(x1) : "l"(ax));
    asm("mov.b64 {%0,%1}, %2;" : "=r"(y0), "=r"(y1) : "l"(ay));

    float dv = dinv[node];
    float4 bb = ((const float4*)bias)[lane];
    float4 o;
    o.x = __uint_as_float(x0) * dv + bb.x;
    o.y = __uint_as_float(x1) * dv + bb.y;
    o.z = __uint_as_float(y0) * dv + bb.z;
    o.w = __uint_as_float(y1) * dv + bb.w;
    if (do_relu) {
        o.x = fmaxf(o.x, 0.f); o.y = fmaxf(o.y, 0.f);
        o.z = fmaxf(o.z, 0.f); o.w = fmaxf(o.w, 0.f);
    }
    out[(size_t)node * 32 + lane] = o;
}

// ---------------------------------------------------------------------------
extern "C" void kernel_launch(void* const* d_in, const int* in_sizes, int n_in,
                              void* d_out, int out_size) {
    const float* x  = (const float*)d_in[0];
    const void*  ei = (const void*) d_in[1];
    const float* W1 = (const float*)d_in[2];
    const float* b1 = (const float*)d_in[3];
    const float* W2 = (const float*)d_in[4];
    const float* b2 = (const float*)d_in[5];
    float* out = (float*)d_out;

    int n = in_sizes[0] / D;
    int E = in_sizes[1] / 2;

    float *dinv, *gbuf, *h1;
    int *cnt, *off, *bsum, *csr;
    unsigned short *w1h, *w1l, *w2h, *w2l;
    cudaGetSymbolAddress((void**)&dinv, g_dinv);
    cudaGetSymbolAddress((void**)&gbuf, g_gbuf);
    cudaGetSymbolAddress((void**)&h1,   g_h1);
    cudaGetSymbolAddress((void**)&cnt,  g_cnt);
    cudaGetSymbolAddress((void**)&off,  g_off);
    cudaGetSymbolAddress((void**)&bsum, g_bsum);
    cudaGetSymbolAddress((void**)&csr,  g_csr);
    cudaGetSymbolAddress((void**)&w1h,  g_w1h);
    cudaGetSymbolAddress((void**)&w1l,  g_w1l);
    cudaGetSymbolAddress((void**)&w2h,  g_w2h);
    cudaGetSymbolAddress((void**)&w2l,  g_w2l);

    static int smem_set = 0;
    if (!smem_set) {
        cudaFuncSetAttribute(gemm_mma_kernel,
                             cudaFuncAttributeMaxDynamicSharedMemorySize, SM_TOTAL);
        smem_set = 1;
    }

    int prep_threads = (n > 2 * 128 * 128) ? n : 2 * 128 * 128;
    int nb_prep = (prep_threads + 255) / 256;
    int nb_edge = (E + 255) / 256;
    int nb_scan = (n + SCAN_BLK - 1) / SCAN_BLK;
    int gemm_blocks = (n + 63) / 64;
    long long gthreads = (long long)n * 32;
    int gather_blocks = (int)((gthreads + 255) / 256);

    // 0: prep (detect + zero cnt + weight split, SA layout)
    prep_all_kernel<<<nb_prep, 256>>>(W1, W2, w1h, w1l, w2h, w2l,
                                      (const long long*)ei, E, cnt, n);
    // 1: histogram of dst
    hist_kernel<<<nb_edge, 256>>>(ei, cnt, E);
    // 2: block-local scan + dinv
    scan1_kernel<<<nb_scan, SCAN_BLK>>>(cnt, off, bsum, dinv, n);
    // 3: layer-1 GEMM (profiled slot)
    gemm_mma_kernel<<<gemm_blocks, 256, SM_TOTAL>>>(x, w1h, w1l, dinv, gbuf, n);
    // 4: scan of block sums
    scan2_kernel<<<1, SCAN_BLK>>>(bsum, nb_scan);
    // 5: CSR fill
    fill_kernel<<<nb_edge, 256>>>(ei, off, bsum, csr, E);
    // 6: layer-1 gather
    gather_kernel<<<gather_blocks, 256>>>(csr, off, bsum, (const ulonglong2*)gbuf,
                                          dinv, b1, (float4*)h1, n, 1);
    // 7: layer-2 GEMM
    gemm_mma_kernel<<<gemm_blocks, 256, SM_TOTAL>>>(h1, w2h, w2l, dinv, gbuf, n);
    // 8: layer-2 gather
    gather_kernel<<<gather_blocks, 256>>>(csr, off, bsum, (const ulonglong2*)gbuf,
                                          dinv, b2, (float4*)out, n, 0);
}